// round 6
// baseline (speedup 1.0000x reference)
#include <cuda_runtime.h>
#include <cuda_fp16.h>
#include <cstdint>

typedef unsigned long long u64;
typedef unsigned u32;

// ================= per-point separable layer0 precompute (fp32) =================
__device__ float g_A0[1024 * 32];   // feat@l0_fc0_w[0:40] + b0  (i part)
__device__ float g_B0[1024 * 32];   // feat@l0_fc0_w[40:80]      (j part)
__device__ float g_A1[1024 * 32];   // feat@l0_fc1_w[0:40] + b1
__device__ float g_B1[1024 * 32];

// ================= weight B-fragments (single fp16) =================
#define T_L0W2  0    // 2kt x 4nt
#define T_L1W1  8
#define T_L1W2  16
#define T_L2W0  24   // 2kt x 2nt
#define T_L2W1  28
#define T_L2W2  32   // 1kt x 2nt
#define T_FW    34   // 1kt x 9nt (N=66 pad 72)
#define N_TILES 43

__device__ u64 g_frag[N_TILES * 32];

__device__ __forceinline__ u32 h16b(float v) {
    return (u32)__half_as_ushort(__float2half_rn(v));
}

// ---- fused prep: blocks [0,256) = per-point tables; blocks [256,267) = frags ----
__global__ void prep(const float* __restrict__ feat,
                     const float* __restrict__ w0, const float* __restrict__ b0,
                     const float* __restrict__ w1, const float* __restrict__ b1,
                     const float* __restrict__ l0w2, const float* __restrict__ l1w1,
                     const float* __restrict__ l1w2, const float* __restrict__ l2w0,
                     const float* __restrict__ l2w1, const float* __restrict__ l2w2,
                     const float* __restrict__ fw) {
    int b = blockIdx.x;
    if (b < 256) {
        int t = b * 256 + threadIdx.x;          // 65536 threads
        int i = t >> 6, rem = t & 63, sel = rem >> 5, c = rem & 31;
        const float* f = feat + i * 40;
        const float* w = sel ? w1 : w0;
        float a = sel ? b1[c] : b0[c], bo = 0.f;
#pragma unroll 8
        for (int k = 0; k < 40; k++) {
            float fv = f[k];
            a  = fmaf(fv, w[k * 32 + c],        a);
            bo = fmaf(fv, w[(k + 40) * 32 + c], bo);
        }
        if (sel) { g_A1[i * 32 + c] = a; g_B1[i * 32 + c] = bo; }
        else     { g_A0[i * 32 + c] = a; g_B0[i * 32 + c] = bo; }
    } else {
        int e = (b - 256) * 256 + threadIdx.x;
        if (e >= N_TILES * 32) return;
        struct Spec { const float* w; int K, N, nnt, base, ntiles; };
        Spec sp[7] = {
            {l0w2, 32, 32, 4, T_L0W2, 8},
            {l1w1, 32, 32, 4, T_L1W1, 8},
            {l1w2, 32, 32, 4, T_L1W2, 8},
            {l2w0, 32, 16, 2, T_L2W0, 4},
            {l2w1, 32, 16, 2, T_L2W1, 4},
            {l2w2, 16, 16, 2, T_L2W2, 2},
            {fw,   16, 66, 9, T_FW,   9},
        };
        int tile = e >> 5, lane = e & 31;
        int si = 0;
        for (int q = 0; q < 7; q++)
            if (tile >= sp[q].base && tile < sp[q].base + sp[q].ntiles) si = q;
        const float* w = sp[si].w;
        int K = sp[si].K, N = sp[si].N, nnt = sp[si].nnt;
        int lt = tile - sp[si].base, kt = lt / nnt, nt = lt % nnt;
        int n = nt * 8 + (lane >> 2), cc = lane & 3;
        int ks[4] = {kt * 16 + 2 * cc, kt * 16 + 2 * cc + 1,
                     kt * 16 + 2 * cc + 8, kt * 16 + 2 * cc + 9};
        u32 bits[4];
#pragma unroll
        for (int q = 0; q < 4; q++) {
            int k = ks[q];
            float v = (k < K && n < N) ? w[k * N + n] : 0.f;
            bits[q] = h16b(v);
        }
        u32 lo = (bits[1] << 16) | bits[0];
        u32 hi = (bits[3] << 16) | bits[2];
        g_frag[e] = ((u64)hi << 32) | (u64)lo;
    }
}

// ================= MMA helpers (fp16 in, fp32 acc) =================
__device__ __forceinline__ void mma_acc(float c[4], const u32 a[4], u64 b) {
    u32 b0 = (u32)b, b1 = (u32)(b >> 32);
    asm volatile("mma.sync.aligned.m16n8k16.row.col.f32.f16.f16.f32 "
        "{%0,%1,%2,%3}, {%4,%5,%6,%7}, {%8,%9}, {%0,%1,%2,%3};"
        : "+f"(c[0]), "+f"(c[1]), "+f"(c[2]), "+f"(c[3])
        : "r"(a[0]), "r"(a[1]), "r"(a[2]), "r"(a[3]), "r"(b0), "r"(b1));
}
__device__ __forceinline__ void mma2(float c[4], const u32 ah[4], const u32 al[4], u64 w) {
    mma_acc(c, ah, w);
    mma_acc(c, al, w);
}

// pack (x0 low, x1 high) into fp16x2 hi, residue into lo
__device__ __forceinline__ void split2(float x0, float x1, u32& hi, u32& lo) {
    __half2 h = __floats2half2_rn(x0, x1);
    float2 f = __half22float2(h);
    __half2 l = __floats2half2_rn(x0 - f.x, x1 - f.y);
    hi = *reinterpret_cast<u32*>(&h);
    lo = *reinterpret_cast<u32*>(&l);
}

// D tiles (ntile 2kt, 2kt+1) -> A frag (ktile kt), optional relu
template<bool RELU>
__device__ __forceinline__ void d2a(const float* d0, const float* d1, u32* ah, u32* al) {
    float v0 = d0[0], v1 = d0[1], v2 = d0[2], v3 = d0[3];
    float w0 = d1[0], w1 = d1[1], w2 = d1[2], w3 = d1[3];
    if (RELU) {
        v0 = fmaxf(v0, 0.f); v1 = fmaxf(v1, 0.f); v2 = fmaxf(v2, 0.f); v3 = fmaxf(v3, 0.f);
        w0 = fmaxf(w0, 0.f); w1 = fmaxf(w1, 0.f); w2 = fmaxf(w2, 0.f); w3 = fmaxf(w3, 0.f);
    }
    split2(v0, v1, ah[0], al[0]);
    split2(v2, v3, ah[1], al[1]);
    split2(w0, w1, ah[2], al[2]);
    split2(w2, w3, ah[3], al[3]);
}

// ================= main kernel: warp = 32 pairs (2 m16 tiles) =================
__global__ void __launch_bounds__(128, 4) ppf_main(
    const float* __restrict__ pc, const float* __restrict__ nrm,
    const float* __restrict__ dist,
    const float* __restrict__ fc0w, const float* __restrict__ fc1w,
    const float* __restrict__ l0b2, const float* __restrict__ l1b1,
    const float* __restrict__ l1b2, const float* __restrict__ l2b0,
    const float* __restrict__ l2b1, const float* __restrict__ l2b2,
    const float* __restrict__ fb, float* __restrict__ out)
{
    __shared__ float sppf[4][32][4];
    __shared__ float sW1p[4][32];
    __shared__ float sW0p[4][32];
    __shared__ u64 sfrag[N_TILES * 32];
    const int tid = threadIdx.x;
    const int lane = tid & 31, warp = tid >> 5;
    const int bx = blockIdx.x;
    const int i = bx >> 3;
    const int jb = ((bx & 7) << 7) + (warp << 5);
    const int r = lane >> 2, cc = lane & 3;
    const int col0 = 2 * cc;

    // stage weight fragments + ppf-weight rows into shared
    for (int e = tid; e < N_TILES * 32; e += 128) sfrag[e] = g_frag[e];
    if (tid < 128) {
        sW1p[tid >> 5][tid & 31] = fc1w[80 * 32 + tid];
        sW0p[tid >> 5][tid & 31] = fc0w[80 * 32 + tid];
    }

    // ---- PPF features: lane computes pair (i, jb+lane) ----
    {
        int j = jb + lane;
        float pcix = pc[3 * i], pciy = pc[3 * i + 1], pciz = pc[3 * i + 2];
        float nix = nrm[3 * i], niy = nrm[3 * i + 1], niz = nrm[3 * i + 2];
        float pcjx = pc[3 * j], pcjy = pc[3 * j + 1], pcjz = pc[3 * j + 2];
        float njx = nrm[3 * j], njy = nrm[3 * j + 1], njz = nrm[3 * j + 2];
        float dd = dist[(i << 10) + j];
        float inv = 1.0f / (dd + 1e-7f);
        float xx0 = pcix - pcjx, xx1 = pciy - pcjy, xx2 = pciz - pcjz;
        sppf[warp][lane][0] = (nix * xx0 + niy * xx1 + niz * xx2) * inv;
        sppf[warp][lane][1] = (njx * xx0 + njy * xx1 + njz * xx2) * inv;
        sppf[warp][lane][2] = nix * njx + niy * njy + niz * njz;
        sppf[warp][lane][3] = dd;
    }
    __syncthreads();

    // ppf rows this lane needs (fp32, exact)
    float pA[2][4], pB[2][4];
#pragma unroll
    for (int mt = 0; mt < 2; mt++) {
        int lr = 16 * mt + r;
#pragma unroll
        for (int k = 0; k < 4; k++) {
            pA[mt][k] = sppf[warp][lr][k];
            pB[mt][k] = sppf[warp][lr + 8][k];
        }
    }

    // ---- layer0: X1 = relu(A1[i] + B1[j] + ppf@W1p)  (scalar fp32 ppf GEMM) ----
    float cx[2][4][4];
#pragma unroll
    for (int nt = 0; nt < 4; nt++) {
        int col = 8 * nt + col0;
        float2 av = *(const float2*)(g_A1 + (i << 5) + col);
#pragma unroll
        for (int mt = 0; mt < 2; mt++) {
            int j0 = jb + 16 * mt + r;
            float2 ba = *(const float2*)(g_B1 + (j0 << 5) + col);
            float2 bb = *(const float2*)(g_B1 + ((j0 + 8) << 5) + col);
            float c0 = av.x + ba.x, c1 = av.y + ba.y;
            float c2 = av.x + bb.x, c3 = av.y + bb.y;
#pragma unroll
            for (int k = 0; k < 4; k++) {
                float2 wv = *(const float2*)&sW1p[k][col];
                c0 = fmaf(pA[mt][k], wv.x, c0); c1 = fmaf(pA[mt][k], wv.y, c1);
                c2 = fmaf(pB[mt][k], wv.x, c2); c3 = fmaf(pB[mt][k], wv.y, c3);
            }
            cx[mt][nt][0] = c0; cx[mt][nt][1] = c1; cx[mt][nt][2] = c2; cx[mt][nt][3] = c3;
        }
    }
    u32 x1h[2][2][4], x1l[2][2][4];
#pragma unroll
    for (int mt = 0; mt < 2; mt++)
#pragma unroll
        for (int kt = 0; kt < 2; kt++)
            d2a<true>(cx[mt][2 * kt], cx[mt][2 * kt + 1], x1h[mt][kt], x1l[mt][kt]);

    // ---- residual R0 = A0[i] + B0[j] + ppf@W0p  (reuse cx) ----
#pragma unroll
    for (int nt = 0; nt < 4; nt++) {
        int col = 8 * nt + col0;
        float2 av = *(const float2*)(g_A0 + (i << 5) + col);
#pragma unroll
        for (int mt = 0; mt < 2; mt++) {
            int j0 = jb + 16 * mt + r;
            float2 ba = *(const float2*)(g_B0 + (j0 << 5) + col);
            float2 bb = *(const float2*)(g_B0 + ((j0 + 8) << 5) + col);
            float c0 = av.x + ba.x, c1 = av.y + ba.y;
            float c2 = av.x + bb.x, c3 = av.y + bb.y;
#pragma unroll
            for (int k = 0; k < 4; k++) {
                float2 wv = *(const float2*)&sW0p[k][col];
                c0 = fmaf(pA[mt][k], wv.x, c0); c1 = fmaf(pA[mt][k], wv.y, c1);
                c2 = fmaf(pB[mt][k], wv.x, c2); c3 = fmaf(pB[mt][k], wv.y, c3);
            }
            cx[mt][nt][0] = c0; cx[mt][nt][1] = c1; cx[mt][nt][2] = c2; cx[mt][nt][3] = c3;
        }
    }

    // ---- l0fc2: X2 = X1@W2 + b2 + R0 ----
#pragma unroll
    for (int nt = 0; nt < 4; nt++) {
        float2 bv = *(const float2*)(l0b2 + 8 * nt + col0);
#pragma unroll
        for (int mt = 0; mt < 2; mt++) {
            cx[mt][nt][0] += bv.x; cx[mt][nt][1] += bv.y;
            cx[mt][nt][2] += bv.x; cx[mt][nt][3] += bv.y;
        }
    }
#pragma unroll
    for (int kt = 0; kt < 2; kt++)
#pragma unroll
        for (int nt = 0; nt < 4; nt++) {
            u64 wv = sfrag[(T_L0W2 + kt * 4 + nt) * 32 + lane];
#pragma unroll
            for (int mt = 0; mt < 2; mt++) mma2(cx[mt][nt], x1h[mt][kt], x1l[mt][kt], wv);
        }
    u32 x2h[2][2][4], x2l[2][2][4];
#pragma unroll
    for (int mt = 0; mt < 2; mt++)
#pragma unroll
        for (int kt = 0; kt < 2; kt++)
            d2a<false>(cx[mt][2 * kt], cx[mt][2 * kt + 1], x2h[mt][kt], x2l[mt][kt]);

    // ---- layer1 fc1: H = relu(X2@W1 + b1) ----
    float ch[2][4][4];
#pragma unroll
    for (int nt = 0; nt < 4; nt++) {
        float2 bv = *(const float2*)(l1b1 + 8 * nt + col0);
#pragma unroll
        for (int mt = 0; mt < 2; mt++) {
            ch[mt][nt][0] = bv.x; ch[mt][nt][1] = bv.y;
            ch[mt][nt][2] = bv.x; ch[mt][nt][3] = bv.y;
        }
    }
#pragma unroll
    for (int kt = 0; kt < 2; kt++)
#pragma unroll
        for (int nt = 0; nt < 4; nt++) {
            u64 wv = sfrag[(T_L1W1 + kt * 4 + nt) * 32 + lane];
#pragma unroll
            for (int mt = 0; mt < 2; mt++) mma2(ch[mt][nt], x2h[mt][kt], x2l[mt][kt], wv);
        }
    u32 hh[2][2][4], hl[2][2][4];
#pragma unroll
    for (int mt = 0; mt < 2; mt++)
#pragma unroll
        for (int kt = 0; kt < 2; kt++)
            d2a<true>(ch[mt][2 * kt], ch[mt][2 * kt + 1], hh[mt][kt], hl[mt][kt]);

    // ---- layer1 fc2: X3 = H@W2 + b2 + X2 (accumulate onto cx = X2) ----
#pragma unroll
    for (int nt = 0; nt < 4; nt++) {
        float2 bv = *(const float2*)(l1b2 + 8 * nt + col0);
#pragma unroll
        for (int mt = 0; mt < 2; mt++) {
            cx[mt][nt][0] += bv.x; cx[mt][nt][1] += bv.y;
            cx[mt][nt][2] += bv.x; cx[mt][nt][3] += bv.y;
        }
    }
#pragma unroll
    for (int kt = 0; kt < 2; kt++)
#pragma unroll
        for (int nt = 0; nt < 4; nt++) {
            u64 wv = sfrag[(T_L1W2 + kt * 4 + nt) * 32 + lane];
#pragma unroll
            for (int mt = 0; mt < 2; mt++) mma2(cx[mt][nt], hh[mt][kt], hl[mt][kt], wv);
        }
    u32 x3h[2][2][4], x3l[2][2][4];
#pragma unroll
    for (int mt = 0; mt < 2; mt++)
#pragma unroll
        for (int kt = 0; kt < 2; kt++)
            d2a<false>(cx[mt][2 * kt], cx[mt][2 * kt + 1], x3h[mt][kt], x3l[mt][kt]);

    // ---- layer2 ----
    float ca[2][2][4], cb[2][2][4];
#pragma unroll
    for (int nt = 0; nt < 2; nt++) {
        float2 b0v = *(const float2*)(l2b0 + 8 * nt + col0);
        float2 b1v = *(const float2*)(l2b1 + 8 * nt + col0);
#pragma unroll
        for (int mt = 0; mt < 2; mt++) {
            ca[mt][nt][0] = b0v.x; ca[mt][nt][1] = b0v.y;
            ca[mt][nt][2] = b0v.x; ca[mt][nt][3] = b0v.y;
            cb[mt][nt][0] = b1v.x; cb[mt][nt][1] = b1v.y;
            cb[mt][nt][2] = b1v.x; cb[mt][nt][3] = b1v.y;
        }
    }
#pragma unroll
    for (int kt = 0; kt < 2; kt++)
#pragma unroll
        for (int nt = 0; nt < 2; nt++) {
            u64 w0v = sfrag[(T_L2W0 + kt * 2 + nt) * 32 + lane];
            u64 w1v = sfrag[(T_L2W1 + kt * 2 + nt) * 32 + lane];
#pragma unroll
            for (int mt = 0; mt < 2; mt++) {
                mma2(ca[mt][nt], x3h[mt][kt], x3l[mt][kt], w0v);
                mma2(cb[mt][nt], x3h[mt][kt], x3l[mt][kt], w1v);
            }
        }
    u32 h2h[2][4], h2l[2][4];
#pragma unroll
    for (int mt = 0; mt < 2; mt++) d2a<true>(cb[mt][0], cb[mt][1], h2h[mt], h2l[mt]);
#pragma unroll
    for (int nt = 0; nt < 2; nt++) {
        float2 bv = *(const float2*)(l2b2 + 8 * nt + col0);
#pragma unroll
        for (int mt = 0; mt < 2; mt++) {
            ca[mt][nt][0] += bv.x; ca[mt][nt][1] += bv.y;
            ca[mt][nt][2] += bv.x; ca[mt][nt][3] += bv.y;
        }
        u64 wv = sfrag[(T_L2W2 + nt) * 32 + lane];
#pragma unroll
        for (int mt = 0; mt < 2; mt++) mma2(ca[mt][nt], h2h[mt], h2l[mt], wv);
    }
    u32 x4h[2][4], x4l[2][4];
#pragma unroll
    for (int mt = 0; mt < 2; mt++) d2a<false>(ca[mt][0], ca[mt][1], x4h[mt], x4l[mt]);

    // ---- final: OUT = X4 @ fw + fb  (N=66, 9 n-tiles, direct STG.64) ----
#pragma unroll
    for (int nt = 0; nt < 9; nt++) {
        int col = 8 * nt + col0;
        bool valid = (col < 66);
        float2 bv = valid ? *(const float2*)(fb + col) : make_float2(0.f, 0.f);
        u64 wv = sfrag[(T_FW + nt) * 32 + lane];
#pragma unroll
        for (int mt = 0; mt < 2; mt++) {
            float cf[4] = {bv.x, bv.y, bv.x, bv.y};
            mma2(cf, x4h[mt], x4l[mt], wv);
            if (valid) {
                int j0 = jb + 16 * mt + r;
                size_t base = (size_t)((i << 10) + j0) * 66ull + col;
                *(float2*)(out + base) = make_float2(cf[0], cf[1]);
                *(float2*)(out + base + 8ull * 66ull) = make_float2(cf[2], cf[3]);
            }
        }
    }
}

extern "C" void kernel_launch(void* const* d_in, const int* in_sizes, int n_in,
                              void* d_out, int out_size) {
    const float* pc   = (const float*)d_in[0];
    const float* nrm  = (const float*)d_in[1];
    const float* dist = (const float*)d_in[2];
    const float* feat = (const float*)d_in[3];
    const float* w0   = (const float*)d_in[4];   const float* b0   = (const float*)d_in[5];
    const float* w1   = (const float*)d_in[6];   const float* b1   = (const float*)d_in[7];
    const float* l0w2 = (const float*)d_in[8];   const float* l0b2 = (const float*)d_in[9];
    const float* l1w1 = (const float*)d_in[10];  const float* l1b1 = (const float*)d_in[11];
    const float* l1w2 = (const float*)d_in[12];  const float* l1b2 = (const float*)d_in[13];
    const float* l2w0 = (const float*)d_in[14];  const float* l2b0 = (const float*)d_in[15];
    const float* l2w1 = (const float*)d_in[16];  const float* l2b1 = (const float*)d_in[17];
    const float* l2w2 = (const float*)d_in[18];  const float* l2b2 = (const float*)d_in[19];
    const float* fw   = (const float*)d_in[20];  const float* fb   = (const float*)d_in[21];
    float* out = (float*)d_out;

    prep<<<267, 256>>>(feat, w0, b0, w1, b1,
                       l0w2, l1w1, l1w2, l2w0, l2w1, l2w2, fw);
    ppf_main<<<8192, 128>>>(pc, nrm, dist, w0, w1,
                            l0b2, l1b1, l1b2, l2b0, l2b1, l2b2, fb, out);
}

// round 7
// speedup vs baseline: 1.1002x; 1.1002x over previous
#include <cuda_runtime.h>
#include <cuda_fp16.h>
#include <cstdint>

typedef unsigned long long u64;
typedef unsigned u32;

// ================= per-point separable layer0 precompute (fp32) =================
__device__ float g_A0[1024 * 32];   // feat@l0_fc0_w[0:40] + b0  (i part)
__device__ float g_B0[1024 * 32];   // feat@l0_fc0_w[40:80]      (j part)
__device__ float g_A1[1024 * 32];   // feat@l0_fc1_w[0:40] + b1
__device__ float g_B1[1024 * 32];

// ================= weight B-fragments (single fp16) =================
#define T_L0W2  0    // 2kt x 4nt
#define T_L1W1  8
#define T_L1W2  16
#define T_L2W0  24   // 2kt x 2nt
#define T_L2W1  28
#define T_L2W2  32   // 1kt x 2nt
#define T_FW    34   // 1kt x 9nt (N=66 pad 72)
#define N_TILES 43

__device__ u64 g_frag[N_TILES * 32];

__device__ __forceinline__ u32 h16b(float v) {
    return (u32)__half_as_ushort(__float2half_rn(v));
}

// ---- fused prep: blocks [0,256) = per-point tables; blocks [256,267) = frags ----
__global__ void prep(const float* __restrict__ feat,
                     const float* __restrict__ w0, const float* __restrict__ b0,
                     const float* __restrict__ w1, const float* __restrict__ b1,
                     const float* __restrict__ l0w2, const float* __restrict__ l1w1,
                     const float* __restrict__ l1w2, const float* __restrict__ l2w0,
                     const float* __restrict__ l2w1, const float* __restrict__ l2w2,
                     const float* __restrict__ fw) {
    int b = blockIdx.x;
    if (b < 256) {
        int t = b * 256 + threadIdx.x;          // 65536 threads
        int i = t >> 6, rem = t & 63, sel = rem >> 5, c = rem & 31;
        const float* f = feat + i * 40;
        const float* w = sel ? w1 : w0;
        float a = sel ? b1[c] : b0[c], bo = 0.f;
#pragma unroll 8
        for (int k = 0; k < 40; k++) {
            float fv = f[k];
            a  = fmaf(fv, w[k * 32 + c],        a);
            bo = fmaf(fv, w[(k + 40) * 32 + c], bo);
        }
        if (sel) { g_A1[i * 32 + c] = a; g_B1[i * 32 + c] = bo; }
        else     { g_A0[i * 32 + c] = a; g_B0[i * 32 + c] = bo; }
    } else {
        int e = (b - 256) * 256 + threadIdx.x;
        if (e >= N_TILES * 32) return;
        struct Spec { const float* w; int K, N, nnt, base, ntiles; };
        Spec sp[7] = {
            {l0w2, 32, 32, 4, T_L0W2, 8},
            {l1w1, 32, 32, 4, T_L1W1, 8},
            {l1w2, 32, 32, 4, T_L1W2, 8},
            {l2w0, 32, 16, 2, T_L2W0, 4},
            {l2w1, 32, 16, 2, T_L2W1, 4},
            {l2w2, 16, 16, 2, T_L2W2, 2},
            {fw,   16, 66, 9, T_FW,   9},
        };
        int tile = e >> 5, lane = e & 31;
        int si = 0;
        for (int q = 0; q < 7; q++)
            if (tile >= sp[q].base && tile < sp[q].base + sp[q].ntiles) si = q;
        const float* w = sp[si].w;
        int K = sp[si].K, N = sp[si].N, nnt = sp[si].nnt;
        int lt = tile - sp[si].base, kt = lt / nnt, nt = lt % nnt;
        int n = nt * 8 + (lane >> 2), cc = lane & 3;
        int ks[4] = {kt * 16 + 2 * cc, kt * 16 + 2 * cc + 1,
                     kt * 16 + 2 * cc + 8, kt * 16 + 2 * cc + 9};
        u32 bits[4];
#pragma unroll
        for (int q = 0; q < 4; q++) {
            int k = ks[q];
            float v = (k < K && n < N) ? w[k * N + n] : 0.f;
            bits[q] = h16b(v);
        }
        u32 lo = (bits[1] << 16) | bits[0];
        u32 hi = (bits[3] << 16) | bits[2];
        g_frag[e] = ((u64)hi << 32) | (u64)lo;
    }
}

// ================= MMA helpers (fp16 in, fp32 acc) =================
__device__ __forceinline__ void mma_acc(float c[4], const u32 a[4], u64 b) {
    u32 b0 = (u32)b, b1 = (u32)(b >> 32);
    asm volatile("mma.sync.aligned.m16n8k16.row.col.f32.f16.f16.f32 "
        "{%0,%1,%2,%3}, {%4,%5,%6,%7}, {%8,%9}, {%0,%1,%2,%3};"
        : "+f"(c[0]), "+f"(c[1]), "+f"(c[2]), "+f"(c[3])
        : "r"(a[0]), "r"(a[1]), "r"(a[2]), "r"(a[3]), "r"(b0), "r"(b1));
}
__device__ __forceinline__ void mma2(float c[4], const u32 ah[4], const u32 al[4], u64 w) {
    mma_acc(c, ah, w);
    mma_acc(c, al, w);
}

// pack (x0 low, x1 high) into fp16x2 hi, residue into lo
__device__ __forceinline__ void split2(float x0, float x1, u32& hi, u32& lo) {
    __half2 h = __floats2half2_rn(x0, x1);
    float2 f = __half22float2(h);
    __half2 l = __floats2half2_rn(x0 - f.x, x1 - f.y);
    hi = *reinterpret_cast<u32*>(&h);
    lo = *reinterpret_cast<u32*>(&l);
}

// D tiles (ntile 2kt, 2kt+1) -> A frag (ktile kt), optional relu
template<bool RELU>
__device__ __forceinline__ void d2a(const float* d0, const float* d1, u32* ah, u32* al) {
    float v0 = d0[0], v1 = d0[1], v2 = d0[2], v3 = d0[3];
    float w0 = d1[0], w1 = d1[1], w2 = d1[2], w3 = d1[3];
    if (RELU) {
        v0 = fmaxf(v0, 0.f); v1 = fmaxf(v1, 0.f); v2 = fmaxf(v2, 0.f); v3 = fmaxf(v3, 0.f);
        w0 = fmaxf(w0, 0.f); w1 = fmaxf(w1, 0.f); w2 = fmaxf(w2, 0.f); w3 = fmaxf(w3, 0.f);
    }
    split2(v0, v1, ah[0], al[0]);
    split2(v2, v3, ah[1], al[1]);
    split2(w0, w1, ah[2], al[2]);
    split2(w2, w3, ah[3], al[3]);
}

// ================= main kernel: warp = 16 pairs (ONE m16 tile) =================
__global__ void __launch_bounds__(128) ppf_main(
    const float* __restrict__ pc, const float* __restrict__ nrm,
    const float* __restrict__ dist,
    const float* __restrict__ fc0w, const float* __restrict__ fc1w,
    const float* __restrict__ l0b2, const float* __restrict__ l1b1,
    const float* __restrict__ l1b2, const float* __restrict__ l2b0,
    const float* __restrict__ l2b1, const float* __restrict__ l2b2,
    const float* __restrict__ fb, float* __restrict__ out)
{
    __shared__ float sppf[4][16][4];
    __shared__ float sW1p[4][32];
    __shared__ float sW0p[4][32];
    const int tid = threadIdx.x;
    const int lane = tid & 31, warp = tid >> 5;
    const int bx = blockIdx.x;
    const int i = bx >> 4;
    const int jb = ((bx & 15) << 6) + (warp << 4);   // 16 j-rows per warp
    const int r = lane >> 2, cc = lane & 3;
    const int col0 = 2 * cc;

    // stage ppf-weight rows (80..83) of fc1/fc0
    if (tid < 128) {
        sW1p[tid >> 5][tid & 31] = fc1w[80 * 32 + tid];
        sW0p[tid >> 5][tid & 31] = fc0w[80 * 32 + tid];
    }

    // ---- PPF features: lanes 0..15 compute pair (i, jb+lane) ----
    if (lane < 16) {
        int j = jb + lane;
        float pcix = pc[3 * i], pciy = pc[3 * i + 1], pciz = pc[3 * i + 2];
        float nix = nrm[3 * i], niy = nrm[3 * i + 1], niz = nrm[3 * i + 2];
        float pcjx = pc[3 * j], pcjy = pc[3 * j + 1], pcjz = pc[3 * j + 2];
        float njx = nrm[3 * j], njy = nrm[3 * j + 1], njz = nrm[3 * j + 2];
        float dd = dist[(i << 10) + j];
        float inv = 1.0f / (dd + 1e-7f);
        float xx0 = pcix - pcjx, xx1 = pciy - pcjy, xx2 = pciz - pcjz;
        sppf[warp][lane][0] = (nix * xx0 + niy * xx1 + niz * xx2) * inv;
        sppf[warp][lane][1] = (njx * xx0 + njy * xx1 + njz * xx2) * inv;
        sppf[warp][lane][2] = nix * njx + niy * njy + niz * njz;
        sppf[warp][lane][3] = dd;
    }
    __syncthreads();

    // ppf rows this lane needs (fp32, exact): rows r and r+8
    float pA[4], pB[4];
#pragma unroll
    for (int k = 0; k < 4; k++) {
        pA[k] = sppf[warp][r][k];
        pB[k] = sppf[warp][r + 8][k];
    }

    // ---- layer0: X1 = relu(A1[i] + B1[j] + ppf@W1p)  (scalar fp32 ppf GEMM) ----
    float cx[4][4];
#pragma unroll
    for (int nt = 0; nt < 4; nt++) {
        int col = 8 * nt + col0;
        float2 av = *(const float2*)(g_A1 + (i << 5) + col);
        int j0 = jb + r;
        float2 ba = *(const float2*)(g_B1 + (j0 << 5) + col);
        float2 bb = *(const float2*)(g_B1 + ((j0 + 8) << 5) + col);
        float c0 = av.x + ba.x, c1 = av.y + ba.y;
        float c2 = av.x + bb.x, c3 = av.y + bb.y;
#pragma unroll
        for (int k = 0; k < 4; k++) {
            float2 wv = *(const float2*)&sW1p[k][col];
            c0 = fmaf(pA[k], wv.x, c0); c1 = fmaf(pA[k], wv.y, c1);
            c2 = fmaf(pB[k], wv.x, c2); c3 = fmaf(pB[k], wv.y, c3);
        }
        cx[nt][0] = c0; cx[nt][1] = c1; cx[nt][2] = c2; cx[nt][3] = c3;
    }
    u32 x1h[2][4], x1l[2][4];
#pragma unroll
    for (int kt = 0; kt < 2; kt++)
        d2a<true>(cx[2 * kt], cx[2 * kt + 1], x1h[kt], x1l[kt]);

    // ---- residual R0 = A0[i] + B0[j] + ppf@W0p  (reuse cx) ----
#pragma unroll
    for (int nt = 0; nt < 4; nt++) {
        int col = 8 * nt + col0;
        float2 av = *(const float2*)(g_A0 + (i << 5) + col);
        int j0 = jb + r;
        float2 ba = *(const float2*)(g_B0 + (j0 << 5) + col);
        float2 bb = *(const float2*)(g_B0 + ((j0 + 8) << 5) + col);
        float c0 = av.x + ba.x, c1 = av.y + ba.y;
        float c2 = av.x + bb.x, c3 = av.y + bb.y;
#pragma unroll
        for (int k = 0; k < 4; k++) {
            float2 wv = *(const float2*)&sW0p[k][col];
            c0 = fmaf(pA[k], wv.x, c0); c1 = fmaf(pA[k], wv.y, c1);
            c2 = fmaf(pB[k], wv.x, c2); c3 = fmaf(pB[k], wv.y, c3);
        }
        cx[nt][0] = c0; cx[nt][1] = c1; cx[nt][2] = c2; cx[nt][3] = c3;
    }

    // ---- l0fc2: X2 = X1@W2 + b2 + R0 ----
#pragma unroll
    for (int nt = 0; nt < 4; nt++) {
        float2 bv = *(const float2*)(l0b2 + 8 * nt + col0);
        cx[nt][0] += bv.x; cx[nt][1] += bv.y;
        cx[nt][2] += bv.x; cx[nt][3] += bv.y;
    }
#pragma unroll
    for (int kt = 0; kt < 2; kt++)
#pragma unroll
        for (int nt = 0; nt < 4; nt++) {
            u64 wv = g_frag[(T_L0W2 + kt * 4 + nt) * 32 + lane];
            mma2(cx[nt], x1h[kt], x1l[kt], wv);
        }
    u32 x2h[2][4], x2l[2][4];
#pragma unroll
    for (int kt = 0; kt < 2; kt++)
        d2a<false>(cx[2 * kt], cx[2 * kt + 1], x2h[kt], x2l[kt]);

    // ---- layer1 fc1: H = relu(X2@W1 + b1) ----
    float ch[4][4];
#pragma unroll
    for (int nt = 0; nt < 4; nt++) {
        float2 bv = *(const float2*)(l1b1 + 8 * nt + col0);
        ch[nt][0] = bv.x; ch[nt][1] = bv.y;
        ch[nt][2] = bv.x; ch[nt][3] = bv.y;
    }
#pragma unroll
    for (int kt = 0; kt < 2; kt++)
#pragma unroll
        for (int nt = 0; nt < 4; nt++) {
            u64 wv = g_frag[(T_L1W1 + kt * 4 + nt) * 32 + lane];
            mma2(ch[nt], x2h[kt], x2l[kt], wv);
        }
    u32 hh[2][4], hl[2][4];
#pragma unroll
    for (int kt = 0; kt < 2; kt++)
        d2a<true>(ch[2 * kt], ch[2 * kt + 1], hh[kt], hl[kt]);

    // ---- layer1 fc2: X3 = H@W2 + b2 + X2 (accumulate onto cx = X2) ----
#pragma unroll
    for (int nt = 0; nt < 4; nt++) {
        float2 bv = *(const float2*)(l1b2 + 8 * nt + col0);
        cx[nt][0] += bv.x; cx[nt][1] += bv.y;
        cx[nt][2] += bv.x; cx[nt][3] += bv.y;
    }
#pragma unroll
    for (int kt = 0; kt < 2; kt++)
#pragma unroll
        for (int nt = 0; nt < 4; nt++) {
            u64 wv = g_frag[(T_L1W2 + kt * 4 + nt) * 32 + lane];
            mma2(cx[nt], hh[kt], hl[kt], wv);
        }
    u32 x3h[2][4], x3l[2][4];
#pragma unroll
    for (int kt = 0; kt < 2; kt++)
        d2a<false>(cx[2 * kt], cx[2 * kt + 1], x3h[kt], x3l[kt]);

    // ---- layer2 ----
    float ca[2][4], cb[2][4];
#pragma unroll
    for (int nt = 0; nt < 2; nt++) {
        float2 b0v = *(const float2*)(l2b0 + 8 * nt + col0);
        float2 b1v = *(const float2*)(l2b1 + 8 * nt + col0);
        ca[nt][0] = b0v.x; ca[nt][1] = b0v.y;
        ca[nt][2] = b0v.x; ca[nt][3] = b0v.y;
        cb[nt][0] = b1v.x; cb[nt][1] = b1v.y;
        cb[nt][2] = b1v.x; cb[nt][3] = b1v.y;
    }
#pragma unroll
    for (int kt = 0; kt < 2; kt++)
#pragma unroll
        for (int nt = 0; nt < 2; nt++) {
            u64 w0v = g_frag[(T_L2W0 + kt * 2 + nt) * 32 + lane];
            u64 w1v = g_frag[(T_L2W1 + kt * 2 + nt) * 32 + lane];
            mma2(ca[nt], x3h[kt], x3l[kt], w0v);
            mma2(cb[nt], x3h[kt], x3l[kt], w1v);
        }
    u32 h2h[4], h2l[4];
    d2a<true>(cb[0], cb[1], h2h, h2l);
#pragma unroll
    for (int nt = 0; nt < 2; nt++) {
        float2 bv = *(const float2*)(l2b2 + 8 * nt + col0);
        ca[nt][0] += bv.x; ca[nt][1] += bv.y;
        ca[nt][2] += bv.x; ca[nt][3] += bv.y;
        u64 wv = g_frag[(T_L2W2 + nt) * 32 + lane];
        mma2(ca[nt], h2h, h2l, wv);
    }
    u32 x4h[4], x4l[4];
    d2a<false>(ca[0], ca[1], x4h, x4l);

    // ---- final: OUT = X4 @ fw + fb  (N=66, 9 n-tiles, direct STG.64) ----
#pragma unroll
    for (int nt = 0; nt < 9; nt++) {
        int col = 8 * nt + col0;
        bool valid = (col < 66);
        float2 bv = valid ? *(const float2*)(fb + col) : make_float2(0.f, 0.f);
        u64 wv = g_frag[(T_FW + nt) * 32 + lane];
        float cf[4] = {bv.x, bv.y, bv.x, bv.y};
        mma2(cf, x4h, x4l, wv);
        if (valid) {
            int j0 = jb + r;
            size_t base = (size_t)((i << 10) + j0) * 66ull + col;
            *(float2*)(out + base) = make_float2(cf[0], cf[1]);
            *(float2*)(out + base + 8ull * 66ull) = make_float2(cf[2], cf[3]);
        }
    }
}

extern "C" void kernel_launch(void* const* d_in, const int* in_sizes, int n_in,
                              void* d_out, int out_size) {
    const float* pc   = (const float*)d_in[0];
    const float* nrm  = (const float*)d_in[1];
    const float* dist = (const float*)d_in[2];
    const float* feat = (const float*)d_in[3];
    const float* w0   = (const float*)d_in[4];   const float* b0   = (const float*)d_in[5];
    const float* w1   = (const float*)d_in[6];   const float* b1   = (const float*)d_in[7];
    const float* l0w2 = (const float*)d_in[8];   const float* l0b2 = (const float*)d_in[9];
    const float* l1w1 = (const float*)d_in[10];  const float* l1b1 = (const float*)d_in[11];
    const float* l1w2 = (const float*)d_in[12];  const float* l1b2 = (const float*)d_in[13];
    const float* l2w0 = (const float*)d_in[14];  const float* l2b0 = (const float*)d_in[15];
    const float* l2w1 = (const float*)d_in[16];  const float* l2b1 = (const float*)d_in[17];
    const float* l2w2 = (const float*)d_in[18];  const float* l2b2 = (const float*)d_in[19];
    const float* fw   = (const float*)d_in[20];  const float* fb   = (const float*)d_in[21];
    float* out = (float*)d_out;

    prep<<<267, 256>>>(feat, w0, b0, w1, b1,
                       l0w2, l1w1, l1w2, l2w0, l2w1, l2w2, fw);
    ppf_main<<<16384, 128>>>(pc, nrm, dist, w0, w1,
                             l0b2, l1b1, l1b2, l2b0, l2b1, l2b2, fb, out);
}

// round 8
// speedup vs baseline: 1.2667x; 1.1513x over previous
#include <cuda_runtime.h>
#include <cuda_fp16.h>
#include <cstdint>

typedef unsigned long long u64;
typedef unsigned u32;

// ===== per-point separable layer0 tables, stored PERMUTED into fragment order =====
// index: point*32 + cc*8 + nt*2 + e   (original col c = 8*nt + 2*cc + e)
__device__ float g_A0[1024 * 32];
__device__ float g_B0[1024 * 32];
__device__ float g_A1[1024 * 32];
__device__ float g_B1[1024 * 32];

// ================= weight B-fragments (single fp16) =================
#define T_L0W2  0    // 2kt x 4nt
#define T_L1W1  8
#define T_L1W2  16
#define T_L2W0  24   // 2kt x 2nt
#define T_L2W1  28
#define T_L2W2  32   // 1kt x 2nt
#define T_FW    34   // 1kt x 9nt (N=66 pad 72)
#define N_TILES 43

__device__ u64 g_frag[N_TILES * 32];

__device__ __forceinline__ u32 h16b(float v) {
    return (u32)__half_as_ushort(__float2half_rn(v));
}

// ---- fused prep: blocks [0,256) = per-point tables; blocks [256,267) = frags ----
__global__ void prep(const float* __restrict__ feat,
                     const float* __restrict__ w0, const float* __restrict__ b0,
                     const float* __restrict__ w1, const float* __restrict__ b1,
                     const float* __restrict__ l0w2, const float* __restrict__ l1w1,
                     const float* __restrict__ l1w2, const float* __restrict__ l2w0,
                     const float* __restrict__ l2w1, const float* __restrict__ l2w2,
                     const float* __restrict__ fw) {
    int b = blockIdx.x;
    if (b < 256) {
        int t = b * 256 + threadIdx.x;          // 65536 threads
        int i = t >> 6, rem = t & 63, sel = rem >> 5, c = rem & 31;
        const float* f = feat + i * 40;
        const float* w = sel ? w1 : w0;
        float a = sel ? b1[c] : b0[c], bo = 0.f;
#pragma unroll 8
        for (int k = 0; k < 40; k++) {
            float fv = f[k];
            a  = fmaf(fv, w[k * 32 + c],        a);
            bo = fmaf(fv, w[(k + 40) * 32 + c], bo);
        }
        // permuted index: c = 8*nt + 2*cc + e  ->  cc*8 + nt*2 + e
        int p = ((c & 7) >> 1) * 8 + (c >> 3) * 2 + (c & 1);
        if (sel) { g_A1[i * 32 + p] = a; g_B1[i * 32 + p] = bo; }
        else     { g_A0[i * 32 + p] = a; g_B0[i * 32 + p] = bo; }
    } else {
        int e = (b - 256) * 256 + threadIdx.x;
        if (e >= N_TILES * 32) return;
        struct Spec { const float* w; int K, N, nnt, base, ntiles; };
        Spec sp[7] = {
            {l0w2, 32, 32, 4, T_L0W2, 8},
            {l1w1, 32, 32, 4, T_L1W1, 8},
            {l1w2, 32, 32, 4, T_L1W2, 8},
            {l2w0, 32, 16, 2, T_L2W0, 4},
            {l2w1, 32, 16, 2, T_L2W1, 4},
            {l2w2, 16, 16, 2, T_L2W2, 2},
            {fw,   16, 66, 9, T_FW,   9},
        };
        int tile = e >> 5, lane = e & 31;
        int si = 0;
        for (int q = 0; q < 7; q++)
            if (tile >= sp[q].base && tile < sp[q].base + sp[q].ntiles) si = q;
        const float* w = sp[si].w;
        int K = sp[si].K, N = sp[si].N, nnt = sp[si].nnt;
        int lt = tile - sp[si].base, kt = lt / nnt, nt = lt % nnt;
        int n = nt * 8 + (lane >> 2), cc = lane & 3;
        int ks[4] = {kt * 16 + 2 * cc, kt * 16 + 2 * cc + 1,
                     kt * 16 + 2 * cc + 8, kt * 16 + 2 * cc + 9};
        u32 bits[4];
#pragma unroll
        for (int q = 0; q < 4; q++) {
            int k = ks[q];
            float v = (k < K && n < N) ? w[k * N + n] : 0.f;
            bits[q] = h16b(v);
        }
        u32 lo = (bits[1] << 16) | bits[0];
        u32 hi = (bits[3] << 16) | bits[2];
        g_frag[e] = ((u64)hi << 32) | (u64)lo;
    }
}

// ================= MMA helpers (fp16 in, fp32 acc) =================
__device__ __forceinline__ void mma_acc(float c[4], const u32 a[4], u64 b) {
    u32 b0 = (u32)b, b1 = (u32)(b >> 32);
    asm volatile("mma.sync.aligned.m16n8k16.row.col.f32.f16.f16.f32 "
        "{%0,%1,%2,%3}, {%4,%5,%6,%7}, {%8,%9}, {%0,%1,%2,%3};"
        : "+f"(c[0]), "+f"(c[1]), "+f"(c[2]), "+f"(c[3])
        : "r"(a[0]), "r"(a[1]), "r"(a[2]), "r"(a[3]), "r"(b0), "r"(b1));
}
__device__ __forceinline__ void mma2(float c[4], const u32 ah[4], const u32 al[4], u64 w) {
    mma_acc(c, ah, w);
    mma_acc(c, al, w);
}

// pack (x0 low, x1 high) into fp16x2 hi, residue into lo
__device__ __forceinline__ void split2(float x0, float x1, u32& hi, u32& lo) {
    __half2 h = __floats2half2_rn(x0, x1);
    float2 f = __half22float2(h);
    __half2 l = __floats2half2_rn(x0 - f.x, x1 - f.y);
    hi = *reinterpret_cast<u32*>(&h);
    lo = *reinterpret_cast<u32*>(&l);
}

// D tiles (ntile 2kt, 2kt+1) -> A frag (ktile kt), optional relu
template<bool RELU>
__device__ __forceinline__ void d2a(const float* d0, const float* d1, u32* ah, u32* al) {
    float v0 = d0[0], v1 = d0[1], v2 = d0[2], v3 = d0[3];
    float w0 = d1[0], w1 = d1[1], w2 = d1[2], w3 = d1[3];
    if (RELU) {
        v0 = fmaxf(v0, 0.f); v1 = fmaxf(v1, 0.f); v2 = fmaxf(v2, 0.f); v3 = fmaxf(v3, 0.f);
        w0 = fmaxf(w0, 0.f); w1 = fmaxf(w1, 0.f); w2 = fmaxf(w2, 0.f); w3 = fmaxf(w3, 0.f);
    }
    split2(v0, v1, ah[0], al[0]);
    split2(v2, v3, ah[1], al[1]);
    split2(w0, w1, ah[2], al[2]);
    split2(w2, w3, ah[3], al[3]);
}

// ================= main kernel: warp = 16 pairs (ONE m16 tile) =================
__global__ void __launch_bounds__(128) ppf_main(
    const float* __restrict__ pc, const float* __restrict__ nrm,
    const float* __restrict__ dist,
    const float* __restrict__ fc0w, const float* __restrict__ fc1w,
    const float* __restrict__ l0b2, const float* __restrict__ l1b1,
    const float* __restrict__ l1b2, const float* __restrict__ l2b0,
    const float* __restrict__ l2b1, const float* __restrict__ l2b2,
    const float* __restrict__ fb, float* __restrict__ out)
{
    __shared__ float sppf[4][16][4];
    __shared__ float sW1p[4][32];
    __shared__ float sW0p[4][32];
    __shared__ float sout[4][16][72];   // padded rows (stride 72) for low-conflict STS
    const int tid = threadIdx.x;
    const int lane = tid & 31, warp = tid >> 5;
    const int bx = blockIdx.x;
    const int i = bx >> 4;
    const int jb = ((bx & 15) << 6) + (warp << 4);   // 16 j-rows per warp
    const int r = lane >> 2, cc = lane & 3;
    const int col0 = 2 * cc;

    // stage ppf-weight rows (80..83) of fc1/fc0
    if (tid < 128) {
        sW1p[tid >> 5][tid & 31] = fc1w[80 * 32 + tid];
        sW0p[tid >> 5][tid & 31] = fc0w[80 * 32 + tid];
    }

    // ---- PPF features: lanes 0..15 compute pair (i, jb+lane) ----
    if (lane < 16) {
        int j = jb + lane;
        float pcix = pc[3 * i], pciy = pc[3 * i + 1], pciz = pc[3 * i + 2];
        float nix = nrm[3 * i], niy = nrm[3 * i + 1], niz = nrm[3 * i + 2];
        float pcjx = pc[3 * j], pcjy = pc[3 * j + 1], pcjz = pc[3 * j + 2];
        float njx = nrm[3 * j], njy = nrm[3 * j + 1], njz = nrm[3 * j + 2];
        float dd = dist[(i << 10) + j];
        float inv = 1.0f / (dd + 1e-7f);
        float xx0 = pcix - pcjx, xx1 = pciy - pcjy, xx2 = pciz - pcjz;
        sppf[warp][lane][0] = (nix * xx0 + niy * xx1 + niz * xx2) * inv;
        sppf[warp][lane][1] = (njx * xx0 + njy * xx1 + njz * xx2) * inv;
        sppf[warp][lane][2] = nix * njx + niy * njy + niz * njz;
        sppf[warp][lane][3] = dd;
    }
    __syncthreads();

    // ppf rows this lane needs (fp32, exact): rows r and r+8
    float pA[4], pB[4];
#pragma unroll
    for (int k = 0; k < 4; k++) {
        pA[k] = sppf[warp][r][k];
        pB[k] = sppf[warp][r + 8][k];
    }

    const int j0 = jb + r;
    const int tb = (cc << 3);   // permuted table base offset for this cc

    // ---- layer0: X1 = relu(A1[i] + B1[j] + ppf@W1p)  (scalar fp32 ppf GEMM) ----
    // permuted tables: element [2*nt+e] at point*32 + cc*8
    float a1v[8], b1r[8], b1s[8];
    {
        const float4* Ap = (const float4*)(g_A1 + (i << 5) + tb);
        const float4* Br = (const float4*)(g_B1 + (j0 << 5) + tb);
        const float4* Bs = (const float4*)(g_B1 + ((j0 + 8) << 5) + tb);
        *(float4*)&a1v[0] = Ap[0]; *(float4*)&a1v[4] = Ap[1];
        *(float4*)&b1r[0] = Br[0]; *(float4*)&b1r[4] = Br[1];
        *(float4*)&b1s[0] = Bs[0]; *(float4*)&b1s[4] = Bs[1];
    }
    float cx[4][4];
#pragma unroll
    for (int nt = 0; nt < 4; nt++) {
        int col = 8 * nt + col0;
        float c0 = a1v[2 * nt] + b1r[2 * nt],     c1 = a1v[2 * nt + 1] + b1r[2 * nt + 1];
        float c2 = a1v[2 * nt] + b1s[2 * nt],     c3 = a1v[2 * nt + 1] + b1s[2 * nt + 1];
#pragma unroll
        for (int k = 0; k < 4; k++) {
            float2 wv = *(const float2*)&sW1p[k][col];
            c0 = fmaf(pA[k], wv.x, c0); c1 = fmaf(pA[k], wv.y, c1);
            c2 = fmaf(pB[k], wv.x, c2); c3 = fmaf(pB[k], wv.y, c3);
        }
        cx[nt][0] = c0; cx[nt][1] = c1; cx[nt][2] = c2; cx[nt][3] = c3;
    }
    u32 x1h[2][4], x1l[2][4];
#pragma unroll
    for (int kt = 0; kt < 2; kt++)
        d2a<true>(cx[2 * kt], cx[2 * kt + 1], x1h[kt], x1l[kt]);

    // ---- residual R0 = A0[i] + B0[j] + ppf@W0p  (reuse cx) ----
    {
        const float4* Ap = (const float4*)(g_A0 + (i << 5) + tb);
        const float4* Br = (const float4*)(g_B0 + (j0 << 5) + tb);
        const float4* Bs = (const float4*)(g_B0 + ((j0 + 8) << 5) + tb);
        *(float4*)&a1v[0] = Ap[0]; *(float4*)&a1v[4] = Ap[1];
        *(float4*)&b1r[0] = Br[0]; *(float4*)&b1r[4] = Br[1];
        *(float4*)&b1s[0] = Bs[0]; *(float4*)&b1s[4] = Bs[1];
    }
#pragma unroll
    for (int nt = 0; nt < 4; nt++) {
        int col = 8 * nt + col0;
        float c0 = a1v[2 * nt] + b1r[2 * nt],     c1 = a1v[2 * nt + 1] + b1r[2 * nt + 1];
        float c2 = a1v[2 * nt] + b1s[2 * nt],     c3 = a1v[2 * nt + 1] + b1s[2 * nt + 1];
#pragma unroll
        for (int k = 0; k < 4; k++) {
            float2 wv = *(const float2*)&sW0p[k][col];
            c0 = fmaf(pA[k], wv.x, c0); c1 = fmaf(pA[k], wv.y, c1);
            c2 = fmaf(pB[k], wv.x, c2); c3 = fmaf(pB[k], wv.y, c3);
        }
        cx[nt][0] = c0; cx[nt][1] = c1; cx[nt][2] = c2; cx[nt][3] = c3;
    }

    // ---- l0fc2: X2 = X1@W2 + b2 + R0 ----
#pragma unroll
    for (int nt = 0; nt < 4; nt++) {
        float2 bv = *(const float2*)(l0b2 + 8 * nt + col0);
        cx[nt][0] += bv.x; cx[nt][1] += bv.y;
        cx[nt][2] += bv.x; cx[nt][3] += bv.y;
    }
#pragma unroll
    for (int kt = 0; kt < 2; kt++)
#pragma unroll
        for (int nt = 0; nt < 4; nt++) {
            u64 wv = g_frag[(T_L0W2 + kt * 4 + nt) * 32 + lane];
            mma2(cx[nt], x1h[kt], x1l[kt], wv);
        }
    u32 x2h[2][4], x2l[2][4];
#pragma unroll
    for (int kt = 0; kt < 2; kt++)
        d2a<false>(cx[2 * kt], cx[2 * kt + 1], x2h[kt], x2l[kt]);

    // ---- layer1 fc1: H = relu(X2@W1 + b1) ----
    float ch[4][4];
#pragma unroll
    for (int nt = 0; nt < 4; nt++) {
        float2 bv = *(const float2*)(l1b1 + 8 * nt + col0);
        ch[nt][0] = bv.x; ch[nt][1] = bv.y;
        ch[nt][2] = bv.x; ch[nt][3] = bv.y;
    }
#pragma unroll
    for (int kt = 0; kt < 2; kt++)
#pragma unroll
        for (int nt = 0; nt < 4; nt++) {
            u64 wv = g_frag[(T_L1W1 + kt * 4 + nt) * 32 + lane];
            mma2(ch[nt], x2h[kt], x2l[kt], wv);
        }
    u32 hh[2][4], hl[2][4];
#pragma unroll
    for (int kt = 0; kt < 2; kt++)
        d2a<true>(ch[2 * kt], ch[2 * kt + 1], hh[kt], hl[kt]);

    // ---- layer1 fc2: X3 = H@W2 + b2 + X2 (accumulate onto cx = X2) ----
#pragma unroll
    for (int nt = 0; nt < 4; nt++) {
        float2 bv = *(const float2*)(l1b2 + 8 * nt + col0);
        cx[nt][0] += bv.x; cx[nt][1] += bv.y;
        cx[nt][2] += bv.x; cx[nt][3] += bv.y;
    }
#pragma unroll
    for (int kt = 0; kt < 2; kt++)
#pragma unroll
        for (int nt = 0; nt < 4; nt++) {
            u64 wv = g_frag[(T_L1W2 + kt * 4 + nt) * 32 + lane];
            mma2(cx[nt], hh[kt], hl[kt], wv);
        }
    u32 x3h[2][4], x3l[2][4];
#pragma unroll
    for (int kt = 0; kt < 2; kt++)
        d2a<false>(cx[2 * kt], cx[2 * kt + 1], x3h[kt], x3l[kt]);

    // ---- layer2 ----
    float ca[2][4], cb[2][4];
#pragma unroll
    for (int nt = 0; nt < 2; nt++) {
        float2 b0v = *(const float2*)(l2b0 + 8 * nt + col0);
        float2 b1v = *(const float2*)(l2b1 + 8 * nt + col0);
        ca[nt][0] = b0v.x; ca[nt][1] = b0v.y;
        ca[nt][2] = b0v.x; ca[nt][3] = b0v.y;
        cb[nt][0] = b1v.x; cb[nt][1] = b1v.y;
        cb[nt][2] = b1v.x; cb[nt][3] = b1v.y;
    }
#pragma unroll
    for (int kt = 0; kt < 2; kt++)
#pragma unroll
        for (int nt = 0; nt < 2; nt++) {
            u64 w0v = g_frag[(T_L2W0 + kt * 2 + nt) * 32 + lane];
            u64 w1v = g_frag[(T_L2W1 + kt * 2 + nt) * 32 + lane];
            mma2(ca[nt], x3h[kt], x3l[kt], w0v);
            mma2(cb[nt], x3h[kt], x3l[kt], w1v);
        }
    u32 h2h[4], h2l[4];
    d2a<true>(cb[0], cb[1], h2h, h2l);
#pragma unroll
    for (int nt = 0; nt < 2; nt++) {
        float2 bv = *(const float2*)(l2b2 + 8 * nt + col0);
        ca[nt][0] += bv.x; ca[nt][1] += bv.y;
        ca[nt][2] += bv.x; ca[nt][3] += bv.y;
        u64 wv = g_frag[(T_L2W2 + nt) * 32 + lane];
        mma2(ca[nt], h2h, h2l, wv);
    }
    u32 x4h[4], x4l[4];
    d2a<false>(ca[0], ca[1], x4h, x4l);

    // ---- final: OUT = X4 @ fw + fb -> stage in smem, then dense copy-out ----
#pragma unroll
    for (int nt = 0; nt < 9; nt++) {
        int col = 8 * nt + col0;
        bool valid = (col < 66);
        float2 bv = valid ? *(const float2*)(fb + col) : make_float2(0.f, 0.f);
        u64 wv = g_frag[(T_FW + nt) * 32 + lane];
        float cf[4] = {bv.x, bv.y, bv.x, bv.y};
        mma2(cf, x4h, x4l, wv);
        *(float2*)&sout[warp][r][col]     = make_float2(cf[0], cf[1]);
        *(float2*)&sout[warp][r + 8][col] = make_float2(cf[2], cf[3]);
    }
    __syncwarp();
    // dense copy: 16 rows x 66 floats = 528 float2, coalesced in gmem
    {
        const float* src = &sout[warp][0][0];
        float* dst = out + ((size_t)(i << 10) + (size_t)jb) * 66ull;
#pragma unroll
        for (int it = 0; it < 17; it++) {
            int e = it * 32 + lane;
            if (e < 528) {
                int row = e / 33;
                int c2 = e - row * 33;
                float2 v = *(const float2*)(src + row * 72 + 2 * c2);
                *(float2*)(dst + row * 66 + 2 * c2) = v;
            }
        }
    }
}

extern "C" void kernel_launch(void* const* d_in, const int* in_sizes, int n_in,
                              void* d_out, int out_size) {
    const float* pc   = (const float*)d_in[0];
    const float* nrm  = (const float*)d_in[1];
    const float* dist = (const float*)d_in[2];
    const float* feat = (const float*)d_in[3];
    const float* w0   = (const float*)d_in[4];   const float* b0   = (const float*)d_in[5];
    const float* w1   = (const float*)d_in[6];   const float* b1   = (const float*)d_in[7];
    const float* l0w2 = (const float*)d_in[8];   const float* l0b2 = (const float*)d_in[9];
    const float* l1w1 = (const float*)d_in[10];  const float* l1b1 = (const float*)d_in[11];
    const float* l1w2 = (const float*)d_in[12];  const float* l1b2 = (const float*)d_in[13];
    const float* l2w0 = (const float*)d_in[14];  const float* l2b0 = (const float*)d_in[15];
    const float* l2w1 = (const float*)d_in[16];  const float* l2b1 = (const float*)d_in[17];
    const float* l2w2 = (const float*)d_in[18];  const float* l2b2 = (const float*)d_in[19];
    const float* fw   = (const float*)d_in[20];  const float* fb   = (const float*)d_in[21];
    float* out = (float*)d_out;

    prep<<<267, 256>>>(feat, w0, b0, w1, b1,
                       l0w2, l1w1, l1w2, l2w0, l2w1, l2w2, fw);
    ppf_main<<<16384, 128>>>(pc, nrm, dist, w0, w1,
                             l0b2, l1b1, l1b2, l2b0, l2b1, l2b2, fb, out);
}

// round 9
// speedup vs baseline: 1.3184x; 1.0408x over previous
#include <cuda_runtime.h>
#include <cuda_fp16.h>
#include <cstdint>

typedef unsigned long long u64;
typedef unsigned u32;

// ===== per-point separable layer0 tables, stored PERMUTED into fragment order =====
// index: point*32 + cc*8 + nt*2 + e   (original col c = 8*nt + 2*cc + e)
__device__ float g_A0[1024 * 32];
__device__ float g_B0[1024 * 32];
__device__ float g_A1[1024 * 32];
__device__ float g_B1[1024 * 32];

// ================= weight B-fragments (single fp16) =================
#define T_L0W2  0    // 2kt x 4nt
#define T_L1W1  8
#define T_L1W2  16
#define T_L2W0  24   // 2kt x 2nt
#define T_L2W1  28
#define T_L2W2  32   // 1kt x 2nt
#define T_FW    34   // 1kt x 9nt (N=66 pad 72)
#define N_TILES 43

__device__ u64 g_frag[N_TILES * 32];

__device__ __forceinline__ u32 h16b(float v) {
    return (u32)__half_as_ushort(__float2half_rn(v));
}

// ---- fused prep: blocks [0,256) = per-point tables; blocks [256,267) = frags ----
__global__ void prep(const float* __restrict__ feat,
                     const float* __restrict__ w0, const float* __restrict__ b0,
                     const float* __restrict__ w1, const float* __restrict__ b1,
                     const float* __restrict__ l0w2, const float* __restrict__ l1w1,
                     const float* __restrict__ l1w2, const float* __restrict__ l2w0,
                     const float* __restrict__ l2w1, const float* __restrict__ l2w2,
                     const float* __restrict__ fw) {
    int b = blockIdx.x;
    if (b < 256) {
        int t = b * 256 + threadIdx.x;          // 65536 threads
        int i = t >> 6, rem = t & 63, sel = rem >> 5, c = rem & 31;
        const float* f = feat + i * 40;
        const float* w = sel ? w1 : w0;
        float a = sel ? b1[c] : b0[c], bo = 0.f;
#pragma unroll
        for (int k = 0; k < 40; k++) {
            float fv = f[k];
            a  = fmaf(fv, w[k * 32 + c],        a);
            bo = fmaf(fv, w[(k + 40) * 32 + c], bo);
        }
        // permuted index: c = 8*nt + 2*cc + e  ->  cc*8 + nt*2 + e
        int p = ((c & 7) >> 1) * 8 + (c >> 3) * 2 + (c & 1);
        if (sel) { g_A1[i * 32 + p] = a; g_B1[i * 32 + p] = bo; }
        else     { g_A0[i * 32 + p] = a; g_B0[i * 32 + p] = bo; }
    } else {
        int e = (b - 256) * 256 + threadIdx.x;
        if (e >= N_TILES * 32) return;
        struct Spec { const float* w; int K, N, nnt, base, ntiles; };
        Spec sp[7] = {
            {l0w2, 32, 32, 4, T_L0W2, 8},
            {l1w1, 32, 32, 4, T_L1W1, 8},
            {l1w2, 32, 32, 4, T_L1W2, 8},
            {l2w0, 32, 16, 2, T_L2W0, 4},
            {l2w1, 32, 16, 2, T_L2W1, 4},
            {l2w2, 16, 16, 2, T_L2W2, 2},
            {fw,   16, 66, 9, T_FW,   9},
        };
        int tile = e >> 5, lane = e & 31;
        int si = 0;
        for (int q = 0; q < 7; q++)
            if (tile >= sp[q].base && tile < sp[q].base + sp[q].ntiles) si = q;
        const float* w = sp[si].w;
        int K = sp[si].K, N = sp[si].N, nnt = sp[si].nnt;
        int lt = tile - sp[si].base, kt = lt / nnt, nt = lt % nnt;
        int n = nt * 8 + (lane >> 2), cc = lane & 3;
        int ks[4] = {kt * 16 + 2 * cc, kt * 16 + 2 * cc + 1,
                     kt * 16 + 2 * cc + 8, kt * 16 + 2 * cc + 9};
        u32 bits[4];
#pragma unroll
        for (int q = 0; q < 4; q++) {
            int k = ks[q];
            float v = (k < K && n < N) ? w[k * N + n] : 0.f;
            bits[q] = h16b(v);
        }
        u32 lo = (bits[1] << 16) | bits[0];
        u32 hi = (bits[3] << 16) | bits[2];
        g_frag[e] = ((u64)hi << 32) | (u64)lo;
    }
}

// ================= MMA helpers (fp16 in, fp32 acc) =================
__device__ __forceinline__ void mma_acc(float c[4], const u32 a[4], u64 b) {
    u32 b0 = (u32)b, b1 = (u32)(b >> 32);
    asm volatile("mma.sync.aligned.m16n8k16.row.col.f32.f16.f16.f32 "
        "{%0,%1,%2,%3}, {%4,%5,%6,%7}, {%8,%9}, {%0,%1,%2,%3};"
        : "+f"(c[0]), "+f"(c[1]), "+f"(c[2]), "+f"(c[3])
        : "r"(a[0]), "r"(a[1]), "r"(a[2]), "r"(a[3]), "r"(b0), "r"(b1));
}
__device__ __forceinline__ void mma2(float c[4], const u32 ah[4], const u32 al[4], u64 w) {
    mma_acc(c, ah, w);
    mma_acc(c, al, w);
}

// pack (x0 low, x1 high) into fp16x2 hi, residue into lo
__device__ __forceinline__ void split2(float x0, float x1, u32& hi, u32& lo) {
    __half2 h = __floats2half2_rn(x0, x1);
    float2 f = __half22float2(h);
    __half2 l = __floats2half2_rn(x0 - f.x, x1 - f.y);
    hi = *reinterpret_cast<u32*>(&h);
    lo = *reinterpret_cast<u32*>(&l);
}

// D tiles (ntile 2kt, 2kt+1) -> A frag (ktile kt), optional relu
template<bool RELU>
__device__ __forceinline__ void d2a(const float* d0, const float* d1, u32* ah, u32* al) {
    float v0 = d0[0], v1 = d0[1], v2 = d0[2], v3 = d0[3];
    float w0 = d1[0], w1 = d1[1], w2 = d1[2], w3 = d1[3];
    if (RELU) {
        v0 = fmaxf(v0, 0.f); v1 = fmaxf(v1, 0.f); v2 = fmaxf(v2, 0.f); v3 = fmaxf(v3, 0.f);
        w0 = fmaxf(w0, 0.f); w1 = fmaxf(w1, 0.f); w2 = fmaxf(w2, 0.f); w3 = fmaxf(w3, 0.f);
    }
    split2(v0, v1, ah[0], al[0]);
    split2(v2, v3, ah[1], al[1]);
    split2(w0, w1, ah[2], al[2]);
    split2(w2, w3, ah[3], al[3]);
}

#define SOUT_STRIDE 74   // 74 mod 32 = 10 -> conflict-free row stagger, float2-aligned

// ================= main kernel: warp = 32 pairs (TWO m16 tiles, shared frags) ====
__global__ void __launch_bounds__(128) ppf_main(
    const float* __restrict__ pc, const float* __restrict__ nrm,
    const float* __restrict__ dist,
    const float* __restrict__ fc0w, const float* __restrict__ fc1w,
    const float* __restrict__ l0b2, const float* __restrict__ l1b1,
    const float* __restrict__ l1b2, const float* __restrict__ l2b0,
    const float* __restrict__ l2b1, const float* __restrict__ l2b2,
    const float* __restrict__ fb, float* __restrict__ out)
{
    __shared__ float sppf[4][32][4];
    __shared__ float sW1p[4][32];
    __shared__ float sW0p[4][32];
    __shared__ float sout[4][32][SOUT_STRIDE];
    const int tid = threadIdx.x;
    const int lane = tid & 31, warp = tid >> 5;
    const int bx = blockIdx.x;
    const int i = bx >> 3;
    const int jb = ((bx & 7) << 7) + (warp << 5);   // 32 j-rows per warp
    const int r = lane >> 2, cc = lane & 3;
    const int col0 = 2 * cc;

    // stage ppf-weight rows (80..83) of fc1/fc0
    if (tid < 128) {
        sW1p[tid >> 5][tid & 31] = fc1w[80 * 32 + tid];
        sW0p[tid >> 5][tid & 31] = fc0w[80 * 32 + tid];
    }

    // ---- PPF features: lane computes pair (i, jb+lane) ----
    {
        int j = jb + lane;
        float pcix = pc[3 * i], pciy = pc[3 * i + 1], pciz = pc[3 * i + 2];
        float nix = nrm[3 * i], niy = nrm[3 * i + 1], niz = nrm[3 * i + 2];
        float pcjx = pc[3 * j], pcjy = pc[3 * j + 1], pcjz = pc[3 * j + 2];
        float njx = nrm[3 * j], njy = nrm[3 * j + 1], njz = nrm[3 * j + 2];
        float dd = dist[(i << 10) + j];
        float inv = 1.0f / (dd + 1e-7f);
        float xx0 = pcix - pcjx, xx1 = pciy - pcjy, xx2 = pciz - pcjz;
        sppf[warp][lane][0] = (nix * xx0 + niy * xx1 + niz * xx2) * inv;
        sppf[warp][lane][1] = (njx * xx0 + njy * xx1 + njz * xx2) * inv;
        sppf[warp][lane][2] = nix * njx + niy * njy + niz * njz;
        sppf[warp][lane][3] = dd;
    }
    __syncthreads();

    // ppf rows this lane needs (fp32, exact): per mt, rows 16mt+r and 16mt+r+8
    float pA[2][4], pB[2][4];
#pragma unroll
    for (int mt = 0; mt < 2; mt++)
#pragma unroll
        for (int k = 0; k < 4; k++) {
            pA[mt][k] = sppf[warp][16 * mt + r][k];
            pB[mt][k] = sppf[warp][16 * mt + r + 8][k];
        }

    const int tb = (cc << 3);   // permuted table base offset for this cc

    // ---- layer0: X1 = relu(A1[i] + B1[j] + ppf@W1p)  (scalar fp32 ppf GEMM) ----
    float cx[2][4][4];
#pragma unroll
    for (int c4 = 0; c4 < 2; c4++) {
        float4 av = ((const float4*)(g_A1 + (i << 5) + tb))[c4];
#pragma unroll
        for (int mt = 0; mt < 2; mt++) {
            int j0 = jb + 16 * mt + r;
            float4 br = ((const float4*)(g_B1 + (j0 << 5) + tb))[c4];
            float4 bs = ((const float4*)(g_B1 + ((j0 + 8) << 5) + tb))[c4];
#pragma unroll
            for (int h = 0; h < 2; h++) {
                int nt = 2 * c4 + h;
                int col = 8 * nt + col0;
                float ax = h ? av.z : av.x, ay = h ? av.w : av.y;
                float rx = h ? br.z : br.x, ry = h ? br.w : br.y;
                float sx = h ? bs.z : bs.x, sy = h ? bs.w : bs.y;
                float c0 = ax + rx, c1 = ay + ry, c2 = ax + sx, c3 = ay + sy;
#pragma unroll
                for (int k = 0; k < 4; k++) {
                    float2 wv = *(const float2*)&sW1p[k][col];
                    c0 = fmaf(pA[mt][k], wv.x, c0); c1 = fmaf(pA[mt][k], wv.y, c1);
                    c2 = fmaf(pB[mt][k], wv.x, c2); c3 = fmaf(pB[mt][k], wv.y, c3);
                }
                cx[mt][nt][0] = c0; cx[mt][nt][1] = c1;
                cx[mt][nt][2] = c2; cx[mt][nt][3] = c3;
            }
        }
    }
    u32 x1h[2][2][4], x1l[2][2][4];
#pragma unroll
    for (int mt = 0; mt < 2; mt++)
#pragma unroll
        for (int kt = 0; kt < 2; kt++)
            d2a<true>(cx[mt][2 * kt], cx[mt][2 * kt + 1], x1h[mt][kt], x1l[mt][kt]);

    // ---- residual R0 = A0[i] + B0[j] + ppf@W0p  (reuse cx) ----
#pragma unroll
    for (int c4 = 0; c4 < 2; c4++) {
        float4 av = ((const float4*)(g_A0 + (i << 5) + tb))[c4];
#pragma unroll
        for (int mt = 0; mt < 2; mt++) {
            int j0 = jb + 16 * mt + r;
            float4 br = ((const float4*)(g_B0 + (j0 << 5) + tb))[c4];
            float4 bs = ((const float4*)(g_B0 + ((j0 + 8) << 5) + tb))[c4];
#pragma unroll
            for (int h = 0; h < 2; h++) {
                int nt = 2 * c4 + h;
                int col = 8 * nt + col0;
                float ax = h ? av.z : av.x, ay = h ? av.w : av.y;
                float rx = h ? br.z : br.x, ry = h ? br.w : br.y;
                float sx = h ? bs.z : bs.x, sy = h ? bs.w : bs.y;
                float c0 = ax + rx, c1 = ay + ry, c2 = ax + sx, c3 = ay + sy;
#pragma unroll
                for (int k = 0; k < 4; k++) {
                    float2 wv = *(const float2*)&sW0p[k][col];
                    c0 = fmaf(pA[mt][k], wv.x, c0); c1 = fmaf(pA[mt][k], wv.y, c1);
                    c2 = fmaf(pB[mt][k], wv.x, c2); c3 = fmaf(pB[mt][k], wv.y, c3);
                }
                cx[mt][nt][0] = c0; cx[mt][nt][1] = c1;
                cx[mt][nt][2] = c2; cx[mt][nt][3] = c3;
            }
        }
    }

    // ---- l0fc2: X2 = X1@W2 + b2 + R0 ----
#pragma unroll
    for (int nt = 0; nt < 4; nt++) {
        float2 bv = *(const float2*)(l0b2 + 8 * nt + col0);
#pragma unroll
        for (int mt = 0; mt < 2; mt++) {
            cx[mt][nt][0] += bv.x; cx[mt][nt][1] += bv.y;
            cx[mt][nt][2] += bv.x; cx[mt][nt][3] += bv.y;
        }
    }
#pragma unroll
    for (int kt = 0; kt < 2; kt++)
#pragma unroll
        for (int nt = 0; nt < 4; nt++) {
            u64 wv = g_frag[(T_L0W2 + kt * 4 + nt) * 32 + lane];
            mma2(cx[0][nt], x1h[0][kt], x1l[0][kt], wv);
            mma2(cx[1][nt], x1h[1][kt], x1l[1][kt], wv);
        }
    u32 x2h[2][2][4], x2l[2][2][4];
#pragma unroll
    for (int mt = 0; mt < 2; mt++)
#pragma unroll
        for (int kt = 0; kt < 2; kt++)
            d2a<false>(cx[mt][2 * kt], cx[mt][2 * kt + 1], x2h[mt][kt], x2l[mt][kt]);

    // ---- layer1 fc1: H = relu(X2@W1 + b1) ----
    float ch[2][4][4];
#pragma unroll
    for (int nt = 0; nt < 4; nt++) {
        float2 bv = *(const float2*)(l1b1 + 8 * nt + col0);
#pragma unroll
        for (int mt = 0; mt < 2; mt++) {
            ch[mt][nt][0] = bv.x; ch[mt][nt][1] = bv.y;
            ch[mt][nt][2] = bv.x; ch[mt][nt][3] = bv.y;
        }
    }
#pragma unroll
    for (int kt = 0; kt < 2; kt++)
#pragma unroll
        for (int nt = 0; nt < 4; nt++) {
            u64 wv = g_frag[(T_L1W1 + kt * 4 + nt) * 32 + lane];
            mma2(ch[0][nt], x2h[0][kt], x2l[0][kt], wv);
            mma2(ch[1][nt], x2h[1][kt], x2l[1][kt], wv);
        }
    u32 hh[2][2][4], hl[2][2][4];
#pragma unroll
    for (int mt = 0; mt < 2; mt++)
#pragma unroll
        for (int kt = 0; kt < 2; kt++)
            d2a<true>(ch[mt][2 * kt], ch[mt][2 * kt + 1], hh[mt][kt], hl[mt][kt]);

    // ---- layer1 fc2: X3 = H@W2 + b2 + X2 (accumulate onto cx = X2) ----
#pragma unroll
    for (int nt = 0; nt < 4; nt++) {
        float2 bv = *(const float2*)(l1b2 + 8 * nt + col0);
#pragma unroll
        for (int mt = 0; mt < 2; mt++) {
            cx[mt][nt][0] += bv.x; cx[mt][nt][1] += bv.y;
            cx[mt][nt][2] += bv.x; cx[mt][nt][3] += bv.y;
        }
    }
#pragma unroll
    for (int kt = 0; kt < 2; kt++)
#pragma unroll
        for (int nt = 0; nt < 4; nt++) {
            u64 wv = g_frag[(T_L1W2 + kt * 4 + nt) * 32 + lane];
            mma2(cx[0][nt], hh[0][kt], hl[0][kt], wv);
            mma2(cx[1][nt], hh[1][kt], hl[1][kt], wv);
        }
    u32 x3h[2][2][4], x3l[2][2][4];
#pragma unroll
    for (int mt = 0; mt < 2; mt++)
#pragma unroll
        for (int kt = 0; kt < 2; kt++)
            d2a<false>(cx[mt][2 * kt], cx[mt][2 * kt + 1], x3h[mt][kt], x3l[mt][kt]);

    // ---- layer2 ----
    float ca[2][2][4], cb[2][2][4];
#pragma unroll
    for (int nt = 0; nt < 2; nt++) {
        float2 b0v = *(const float2*)(l2b0 + 8 * nt + col0);
        float2 b1v = *(const float2*)(l2b1 + 8 * nt + col0);
#pragma unroll
        for (int mt = 0; mt < 2; mt++) {
            ca[mt][nt][0] = b0v.x; ca[mt][nt][1] = b0v.y;
            ca[mt][nt][2] = b0v.x; ca[mt][nt][3] = b0v.y;
            cb[mt][nt][0] = b1v.x; cb[mt][nt][1] = b1v.y;
            cb[mt][nt][2] = b1v.x; cb[mt][nt][3] = b1v.y;
        }
    }
#pragma unroll
    for (int kt = 0; kt < 2; kt++)
#pragma unroll
        for (int nt = 0; nt < 2; nt++) {
            u64 w0v = g_frag[(T_L2W0 + kt * 2 + nt) * 32 + lane];
            u64 w1v = g_frag[(T_L2W1 + kt * 2 + nt) * 32 + lane];
#pragma unroll
            for (int mt = 0; mt < 2; mt++) {
                mma2(ca[mt][nt], x3h[mt][kt], x3l[mt][kt], w0v);
                mma2(cb[mt][nt], x3h[mt][kt], x3l[mt][kt], w1v);
            }
        }
    u32 h2h[2][4], h2l[2][4];
#pragma unroll
    for (int mt = 0; mt < 2; mt++) d2a<true>(cb[mt][0], cb[mt][1], h2h[mt], h2l[mt]);
#pragma unroll
    for (int nt = 0; nt < 2; nt++) {
        float2 bv = *(const float2*)(l2b2 + 8 * nt + col0);
        u64 wv = g_frag[(T_L2W2 + nt) * 32 + lane];
#pragma unroll
        for (int mt = 0; mt < 2; mt++) {
            ca[mt][nt][0] += bv.x; ca[mt][nt][1] += bv.y;
            ca[mt][nt][2] += bv.x; ca[mt][nt][3] += bv.y;
            mma2(ca[mt][nt], h2h[mt], h2l[mt], wv);
        }
    }
    u32 x4h[2][4], x4l[2][4];
#pragma unroll
    for (int mt = 0; mt < 2; mt++) d2a<false>(ca[mt][0], ca[mt][1], x4h[mt], x4l[mt]);

    // ---- final: OUT = X4 @ fw + fb -> stage in smem, then dense copy-out ----
#pragma unroll
    for (int nt = 0; nt < 9; nt++) {
        int col = 8 * nt + col0;
        bool valid = (col < 66);
        float2 bv = valid ? *(const float2*)(fb + col) : make_float2(0.f, 0.f);
        u64 wv = g_frag[(T_FW + nt) * 32 + lane];
#pragma unroll
        for (int mt = 0; mt < 2; mt++) {
            float cf[4] = {bv.x, bv.y, bv.x, bv.y};
            mma2(cf, x4h[mt], x4l[mt], wv);
            *(float2*)&sout[warp][16 * mt + r][col]     = make_float2(cf[0], cf[1]);
            *(float2*)&sout[warp][16 * mt + r + 8][col] = make_float2(cf[2], cf[3]);
        }
    }
    __syncwarp();
    // dense copy: 32 rows x 66 floats = 1056 float2, coalesced in gmem (33 full iters)
    {
        const float* src = &sout[warp][0][0];
        float* dst = out + ((size_t)(i << 10) + (size_t)jb) * 66ull;
#pragma unroll
        for (int it = 0; it < 33; it++) {
            int e = it * 32 + lane;
            int row = e / 33;
            int c2 = e - row * 33;
            float2 v = *(const float2*)(src + row * SOUT_STRIDE + 2 * c2);
            *(float2*)(dst + row * 66 + 2 * c2) = v;
        }
    }
}

extern "C" void kernel_launch(void* const* d_in, const int* in_sizes, int n_in,
                              void* d_out, int out_size) {
    const float* pc   = (const float*)d_in[0];
    const float* nrm  = (const float*)d_in[1];
    const float* dist = (const float*)d_in[2];
    const float* feat = (const float*)d_in[3];
    const float* w0   = (const float*)d_in[4];   const float* b0   = (const float*)d_in[5];
    const float* w1   = (const float*)d_in[6];   const float* b1   = (const float*)d_in[7];
    const float* l0w2 = (const float*)d_in[8];   const float* l0b2 = (const float*)d_in[9];
    const float* l1w1 = (const float*)d_in[10];  const float* l1b1 = (const float*)d_in[11];
    const float* l1w2 = (const float*)d_in[12];  const float* l1b2 = (const float*)d_in[13];
    const float* l2w0 = (const float*)d_in[14];  const float* l2b0 = (const float*)d_in[15];
    const float* l2w1 = (const float*)d_in[16];  const float* l2b1 = (const float*)d_in[17];
    const float* l2w2 = (const float*)d_in[18];  const float* l2b2 = (const float*)d_in[19];
    const float* fw   = (const float*)d_in[20];  const float* fb   = (const float*)d_in[21];
    float* out = (float*)d_out;

    prep<<<267, 256>>>(feat, w0, b0, w1, b1,
                       l0w2, l1w1, l1w2, l2w0, l2w1, l2w2, fw);
    ppf_main<<<8192, 128>>>(pc, nrm, dist, w0, w1,
                            l0b2, l1b1, l1b2, l2b0, l2b1, l2b2, fb, out);
}

// round 10
// speedup vs baseline: 1.3892x; 1.0537x over previous
#include <cuda_runtime.h>
#include <cuda_fp16.h>
#include <cstdint>

typedef unsigned long long u64;
typedef unsigned u32;

// ===== per-point separable layer0 tables, stored PERMUTED into fragment order =====
// index: point*32 + cc*8 + nt*2 + e   (original col c = 8*nt + 2*cc + e)
__device__ float g_A0[1024 * 32];
__device__ float g_B0[1024 * 32];
__device__ float g_A1[1024 * 32];
__device__ float g_B1[1024 * 32];

// ================= weight B-fragments (single fp16) =================
#define T_L0W2  0    // 2kt x 4nt
#define T_L1W1  8
#define T_L1W2  16
#define T_L2W0  24   // 2kt x 2nt
#define T_L2W1  28
#define T_L2W2  32   // 1kt x 2nt
#define T_FW    34   // 1kt x 9nt (N=66 pad 72)
#define N_TILES 43

__device__ u64 g_frag[N_TILES * 32];

__device__ __forceinline__ u32 h16b(float v) {
    return (u32)__half_as_ushort(__float2half_rn(v));
}

// ---- fused prep: blocks [0,256) = per-point tables; blocks [256,267) = frags ----
__global__ void prep(const float* __restrict__ feat,
                     const float* __restrict__ w0, const float* __restrict__ b0,
                     const float* __restrict__ w1, const float* __restrict__ b1,
                     const float* __restrict__ l0w2, const float* __restrict__ l1w1,
                     const float* __restrict__ l1w2, const float* __restrict__ l2w0,
                     const float* __restrict__ l2w1, const float* __restrict__ l2w2,
                     const float* __restrict__ fw) {
    int b = blockIdx.x;
    if (b < 256) {
        int t = b * 256 + threadIdx.x;          // 65536 threads
        int i = t >> 6, rem = t & 63, sel = rem >> 5, c = rem & 31;
        const float* f = feat + i * 40;
        const float* w = sel ? w1 : w0;
        float a = sel ? b1[c] : b0[c], bo = 0.f;
#pragma unroll
        for (int k = 0; k < 40; k++) {
            float fv = f[k];
            a  = fmaf(fv, w[k * 32 + c],        a);
            bo = fmaf(fv, w[(k + 40) * 32 + c], bo);
        }
        // permuted index: c = 8*nt + 2*cc + e  ->  cc*8 + nt*2 + e
        int p = ((c & 7) >> 1) * 8 + (c >> 3) * 2 + (c & 1);
        if (sel) { g_A1[i * 32 + p] = a; g_B1[i * 32 + p] = bo; }
        else     { g_A0[i * 32 + p] = a; g_B0[i * 32 + p] = bo; }
    } else {
        int e = (b - 256) * 256 + threadIdx.x;
        if (e >= N_TILES * 32) return;
        struct Spec { const float* w; int K, N, nnt, base, ntiles; };
        Spec sp[7] = {
            {l0w2, 32, 32, 4, T_L0W2, 8},
            {l1w1, 32, 32, 4, T_L1W1, 8},
            {l1w2, 32, 32, 4, T_L1W2, 8},
            {l2w0, 32, 16, 2, T_L2W0, 4},
            {l2w1, 32, 16, 2, T_L2W1, 4},
            {l2w2, 16, 16, 2, T_L2W2, 2},
            {fw,   16, 66, 9, T_FW,   9},
        };
        int tile = e >> 5, lane = e & 31;
        int si = 0;
        for (int q = 0; q < 7; q++)
            if (tile >= sp[q].base && tile < sp[q].base + sp[q].ntiles) si = q;
        const float* w = sp[si].w;
        int K = sp[si].K, N = sp[si].N, nnt = sp[si].nnt;
        int lt = tile - sp[si].base, kt = lt / nnt, nt = lt % nnt;
        int n = nt * 8 + (lane >> 2), cc = lane & 3;
        int ks[4] = {kt * 16 + 2 * cc, kt * 16 + 2 * cc + 1,
                     kt * 16 + 2 * cc + 8, kt * 16 + 2 * cc + 9};
        u32 bits[4];
#pragma unroll
        for (int q = 0; q < 4; q++) {
            int k = ks[q];
            float v = (k < K && n < N) ? w[k * N + n] : 0.f;
            bits[q] = h16b(v);
        }
        u32 lo = (bits[1] << 16) | bits[0];
        u32 hi = (bits[3] << 16) | bits[2];
        g_frag[e] = ((u64)hi << 32) | (u64)lo;
    }
}

// ================= MMA helpers (fp16 in, fp32 acc) =================
__device__ __forceinline__ void mma_acc(float c[4], const u32 a[4], u64 b) {
    u32 b0 = (u32)b, b1 = (u32)(b >> 32);
    asm volatile("mma.sync.aligned.m16n8k16.row.col.f32.f16.f16.f32 "
        "{%0,%1,%2,%3}, {%4,%5,%6,%7}, {%8,%9}, {%0,%1,%2,%3};"
        : "+f"(c[0]), "+f"(c[1]), "+f"(c[2]), "+f"(c[3])
        : "r"(a[0]), "r"(a[1]), "r"(a[2]), "r"(a[3]), "r"(b0), "r"(b1));
}
__device__ __forceinline__ void mma2(float c[4], const u32 ah[4], const u32 al[4], u64 w) {
    mma_acc(c, ah, w);
    mma_acc(c, al, w);
}

// pack (x0 low, x1 high) into fp16x2 hi, residue into lo
__device__ __forceinline__ void split2(float x0, float x1, u32& hi, u32& lo) {
    __half2 h = __floats2half2_rn(x0, x1);
    float2 f = __half22float2(h);
    __half2 l = __floats2half2_rn(x0 - f.x, x1 - f.y);
    hi = *reinterpret_cast<u32*>(&h);
    lo = *reinterpret_cast<u32*>(&l);
}
// hi-only variant (no residue)
__device__ __forceinline__ u32 split2h(float x0, float x1) {
    __half2 h = __floats2half2_rn(x0, x1);
    return *reinterpret_cast<u32*>(&h);
}
__device__ __forceinline__ float2 h2f(u32 v) {
    __half2 h = *reinterpret_cast<__half2*>(&v);
    return __half22float2(h);
}

// D tiles (ntile 2kt, 2kt+1) -> A frag (ktile kt), optional relu
template<bool RELU>
__device__ __forceinline__ void d2a(const float* d0, const float* d1, u32* ah, u32* al) {
    float v0 = d0[0], v1 = d0[1], v2 = d0[2], v3 = d0[3];
    float w0 = d1[0], w1 = d1[1], w2 = d1[2], w3 = d1[3];
    if (RELU) {
        v0 = fmaxf(v0, 0.f); v1 = fmaxf(v1, 0.f); v2 = fmaxf(v2, 0.f); v3 = fmaxf(v3, 0.f);
        w0 = fmaxf(w0, 0.f); w1 = fmaxf(w1, 0.f); w2 = fmaxf(w2, 0.f); w3 = fmaxf(w3, 0.f);
    }
    split2(v0, v1, ah[0], al[0]);
    split2(v2, v3, ah[1], al[1]);
    split2(w0, w1, ah[2], al[2]);
    split2(w2, w3, ah[3], al[3]);
}
// hi-only A frag
__device__ __forceinline__ void d2a_hi(const float* d0, const float* d1, u32* ah) {
    ah[0] = split2h(d0[0], d0[1]);
    ah[1] = split2h(d0[2], d0[3]);
    ah[2] = split2h(d1[0], d1[1]);
    ah[3] = split2h(d1[2], d1[3]);
}

#define SOUT_STRIDE 74   // 74 mod 32 = 10 -> conflict-free row stagger, float2-aligned

// ================= main kernel: warp = 32 pairs (TWO m16 tiles, shared frags) ====
__global__ void __launch_bounds__(128, 4) ppf_main(
    const float* __restrict__ pc, const float* __restrict__ nrm,
    const float* __restrict__ dist,
    const float* __restrict__ fc0w, const float* __restrict__ fc1w,
    const float* __restrict__ l0b2, const float* __restrict__ l1b1,
    const float* __restrict__ l1b2, const float* __restrict__ l2b0,
    const float* __restrict__ l2b1, const float* __restrict__ l2b2,
    const float* __restrict__ fb, float* __restrict__ out)
{
    __shared__ float sppf[4][32][4];
    __shared__ float sW1p[4][32];
    __shared__ float sW0p[4][32];
    __shared__ float sout[4][32][SOUT_STRIDE];
    const int tid = threadIdx.x;
    const int lane = tid & 31, warp = tid >> 5;
    const int bx = blockIdx.x;
    const int i = bx >> 3;
    const int jb = ((bx & 7) << 7) + (warp << 5);   // 32 j-rows per warp
    const int r = lane >> 2, cc = lane & 3;
    const int col0 = 2 * cc;

    // stage ppf-weight rows (80..83) of fc1/fc0
    if (tid < 128) {
        sW1p[tid >> 5][tid & 31] = fc1w[80 * 32 + tid];
        sW0p[tid >> 5][tid & 31] = fc0w[80 * 32 + tid];
    }

    // ---- PPF features: lane computes pair (i, jb+lane) ----
    {
        int j = jb + lane;
        float pcix = pc[3 * i], pciy = pc[3 * i + 1], pciz = pc[3 * i + 2];
        float nix = nrm[3 * i], niy = nrm[3 * i + 1], niz = nrm[3 * i + 2];
        float pcjx = pc[3 * j], pcjy = pc[3 * j + 1], pcjz = pc[3 * j + 2];
        float njx = nrm[3 * j], njy = nrm[3 * j + 1], njz = nrm[3 * j + 2];
        float dd = dist[(i << 10) + j];
        float inv = 1.0f / (dd + 1e-7f);
        float xx0 = pcix - pcjx, xx1 = pciy - pcjy, xx2 = pciz - pcjz;
        sppf[warp][lane][0] = (nix * xx0 + niy * xx1 + niz * xx2) * inv;
        sppf[warp][lane][1] = (njx * xx0 + njy * xx1 + njz * xx2) * inv;
        sppf[warp][lane][2] = nix * njx + niy * njy + niz * njz;
        sppf[warp][lane][3] = dd;
    }
    __syncthreads();

    // ppf rows this lane needs (fp32, exact): per mt, rows 16mt+r and 16mt+r+8
    float pA[2][4], pB[2][4];
#pragma unroll
    for (int mt = 0; mt < 2; mt++)
#pragma unroll
        for (int k = 0; k < 4; k++) {
            pA[mt][k] = sppf[warp][16 * mt + r][k];
            pB[mt][k] = sppf[warp][16 * mt + r + 8][k];
        }

    const int tb = (cc << 3);   // permuted table base offset for this cc

    // ---- layer0: X1 = relu(A1[i] + B1[j] + ppf@W1p)  (scalar fp32 ppf GEMM) ----
    float cx[2][4][4];
#pragma unroll
    for (int c4 = 0; c4 < 2; c4++) {
        float4 av = ((const float4*)(g_A1 + (i << 5) + tb))[c4];
#pragma unroll
        for (int mt = 0; mt < 2; mt++) {
            int j0 = jb + 16 * mt + r;
            float4 br = ((const float4*)(g_B1 + (j0 << 5) + tb))[c4];
            float4 bs = ((const float4*)(g_B1 + ((j0 + 8) << 5) + tb))[c4];
#pragma unroll
            for (int h = 0; h < 2; h++) {
                int nt = 2 * c4 + h;
                int col = 8 * nt + col0;
                float ax = h ? av.z : av.x, ay = h ? av.w : av.y;
                float rx = h ? br.z : br.x, ry = h ? br.w : br.y;
                float sx = h ? bs.z : bs.x, sy = h ? bs.w : bs.y;
                float c0 = ax + rx, c1 = ay + ry, c2 = ax + sx, c3 = ay + sy;
#pragma unroll
                for (int k = 0; k < 4; k++) {
                    float2 wv = *(const float2*)&sW1p[k][col];
                    c0 = fmaf(pA[mt][k], wv.x, c0); c1 = fmaf(pA[mt][k], wv.y, c1);
                    c2 = fmaf(pB[mt][k], wv.x, c2); c3 = fmaf(pB[mt][k], wv.y, c3);
                }
                cx[mt][nt][0] = c0; cx[mt][nt][1] = c1;
                cx[mt][nt][2] = c2; cx[mt][nt][3] = c3;
            }
        }
    }
    u32 x1h[2][2][4], x1l[2][2][4];
#pragma unroll
    for (int mt = 0; mt < 2; mt++)
#pragma unroll
        for (int kt = 0; kt < 2; kt++)
            d2a<true>(cx[mt][2 * kt], cx[mt][2 * kt + 1], x1h[mt][kt], x1l[mt][kt]);

    // ---- residual R0 = A0[i] + B0[j] + ppf@W0p  (reuse cx) ----
#pragma unroll
    for (int c4 = 0; c4 < 2; c4++) {
        float4 av = ((const float4*)(g_A0 + (i << 5) + tb))[c4];
#pragma unroll
        for (int mt = 0; mt < 2; mt++) {
            int j0 = jb + 16 * mt + r;
            float4 br = ((const float4*)(g_B0 + (j0 << 5) + tb))[c4];
            float4 bs = ((const float4*)(g_B0 + ((j0 + 8) << 5) + tb))[c4];
#pragma unroll
            for (int h = 0; h < 2; h++) {
                int nt = 2 * c4 + h;
                int col = 8 * nt + col0;
                float ax = h ? av.z : av.x, ay = h ? av.w : av.y;
                float rx = h ? br.z : br.x, ry = h ? br.w : br.y;
                float sx = h ? bs.z : bs.x, sy = h ? bs.w : bs.y;
                float c0 = ax + rx, c1 = ay + ry, c2 = ax + sx, c3 = ay + sy;
#pragma unroll
                for (int k = 0; k < 4; k++) {
                    float2 wv = *(const float2*)&sW0p[k][col];
                    c0 = fmaf(pA[mt][k], wv.x, c0); c1 = fmaf(pA[mt][k], wv.y, c1);
                    c2 = fmaf(pB[mt][k], wv.x, c2); c3 = fmaf(pB[mt][k], wv.y, c3);
                }
                cx[mt][nt][0] = c0; cx[mt][nt][1] = c1;
                cx[mt][nt][2] = c2; cx[mt][nt][3] = c3;
            }
        }
    }

    // ---- l0fc2: X2 = X1@W2 + b2 + R0 ----
#pragma unroll
    for (int nt = 0; nt < 4; nt++) {
        float2 bv = *(const float2*)(l0b2 + 8 * nt + col0);
#pragma unroll
        for (int mt = 0; mt < 2; mt++) {
            cx[mt][nt][0] += bv.x; cx[mt][nt][1] += bv.y;
            cx[mt][nt][2] += bv.x; cx[mt][nt][3] += bv.y;
        }
    }
#pragma unroll
    for (int kt = 0; kt < 2; kt++)
#pragma unroll
        for (int nt = 0; nt < 4; nt++) {
            u64 wv = g_frag[(T_L0W2 + kt * 4 + nt) * 32 + lane];
            mma2(cx[0][nt], x1h[0][kt], x1l[0][kt], wv);
            mma2(cx[1][nt], x1h[1][kt], x1l[1][kt], wv);
        }
    u32 x2h[2][2][4], x2l[2][2][4];
#pragma unroll
    for (int mt = 0; mt < 2; mt++)
#pragma unroll
        for (int kt = 0; kt < 2; kt++)
            d2a<false>(cx[mt][2 * kt], cx[mt][2 * kt + 1], x2h[mt][kt], x2l[mt][kt]);

    // ---- layer1 fc1: H = relu(X2@W1 + b1) -- accumulate in cx (X2 lives in x2h/l) ----
#pragma unroll
    for (int nt = 0; nt < 4; nt++) {
        float2 bv = *(const float2*)(l1b1 + 8 * nt + col0);
#pragma unroll
        for (int mt = 0; mt < 2; mt++) {
            cx[mt][nt][0] = bv.x; cx[mt][nt][1] = bv.y;
            cx[mt][nt][2] = bv.x; cx[mt][nt][3] = bv.y;
        }
    }
#pragma unroll
    for (int kt = 0; kt < 2; kt++)
#pragma unroll
        for (int nt = 0; nt < 4; nt++) {
            u64 wv = g_frag[(T_L1W1 + kt * 4 + nt) * 32 + lane];
            mma2(cx[0][nt], x2h[0][kt], x2l[0][kt], wv);
            mma2(cx[1][nt], x2h[1][kt], x2l[1][kt], wv);
        }
    u32 hh[2][2][4], hl[2][2][4];
#pragma unroll
    for (int mt = 0; mt < 2; mt++)
#pragma unroll
        for (int kt = 0; kt < 2; kt++)
            d2a<true>(cx[mt][2 * kt], cx[mt][2 * kt + 1], hh[mt][kt], hl[mt][kt]);

    // ---- layer1 fc2: X3 = H@W2 + b2 + X2 (X2 reconstructed from x2h + x2l) ----
#pragma unroll
    for (int kt = 0; kt < 2; kt++)
#pragma unroll
        for (int h = 0; h < 2; h++) {
            int nt = 2 * kt + h;
            float2 bv = *(const float2*)(l1b2 + 8 * nt + col0);
#pragma unroll
            for (int mt = 0; mt < 2; mt++) {
                float2 hA = h2f(x2h[mt][kt][2 * h]),     lA = h2f(x2l[mt][kt][2 * h]);
                float2 hB = h2f(x2h[mt][kt][2 * h + 1]), lB = h2f(x2l[mt][kt][2 * h + 1]);
                cx[mt][nt][0] = bv.x + hA.x + lA.x;
                cx[mt][nt][1] = bv.y + hA.y + lA.y;
                cx[mt][nt][2] = bv.x + hB.x + lB.x;
                cx[mt][nt][3] = bv.y + hB.y + lB.y;
            }
        }
#pragma unroll
    for (int kt = 0; kt < 2; kt++)
#pragma unroll
        for (int nt = 0; nt < 4; nt++) {
            u64 wv = g_frag[(T_L1W2 + kt * 4 + nt) * 32 + lane];
            mma2(cx[0][nt], hh[0][kt], hl[0][kt], wv);
            mma2(cx[1][nt], hh[1][kt], hl[1][kt], wv);
        }
    u32 x3h[2][2][4], x3l[2][2][4];
#pragma unroll
    for (int mt = 0; mt < 2; mt++)
#pragma unroll
        for (int kt = 0; kt < 2; kt++)
            d2a<false>(cx[mt][2 * kt], cx[mt][2 * kt + 1], x3h[mt][kt], x3l[mt][kt]);

    // ---- layer2 ----
    float ca[2][2][4], cb[2][2][4];
#pragma unroll
    for (int nt = 0; nt < 2; nt++) {
        float2 b0v = *(const float2*)(l2b0 + 8 * nt + col0);
        float2 b1v = *(const float2*)(l2b1 + 8 * nt + col0);
#pragma unroll
        for (int mt = 0; mt < 2; mt++) {
            ca[mt][nt][0] = b0v.x; ca[mt][nt][1] = b0v.y;
            ca[mt][nt][2] = b0v.x; ca[mt][nt][3] = b0v.y;
            cb[mt][nt][0] = b1v.x; cb[mt][nt][1] = b1v.y;
            cb[mt][nt][2] = b1v.x; cb[mt][nt][3] = b1v.y;
        }
    }
#pragma unroll
    for (int kt = 0; kt < 2; kt++)
#pragma unroll
        for (int nt = 0; nt < 2; nt++) {
            u64 w0v = g_frag[(T_L2W0 + kt * 2 + nt) * 32 + lane];
            u64 w1v = g_frag[(T_L2W1 + kt * 2 + nt) * 32 + lane];
#pragma unroll
            for (int mt = 0; mt < 2; mt++) {
                mma2(ca[mt][nt], x3h[mt][kt], x3l[mt][kt], w0v);
                mma2(cb[mt][nt], x3h[mt][kt], x3l[mt][kt], w1v);
            }
        }
    u32 h2h[2][4], h2l[2][4];
#pragma unroll
    for (int mt = 0; mt < 2; mt++) d2a<true>(cb[mt][0], cb[mt][1], h2h[mt], h2l[mt]);
#pragma unroll
    for (int nt = 0; nt < 2; nt++) {
        float2 bv = *(const float2*)(l2b2 + 8 * nt + col0);
        u64 wv = g_frag[(T_L2W2 + nt) * 32 + lane];
#pragma unroll
        for (int mt = 0; mt < 2; mt++) {
            ca[mt][nt][0] += bv.x; ca[mt][nt][1] += bv.y;
            ca[mt][nt][2] += bv.x; ca[mt][nt][3] += bv.y;
            mma2(ca[mt][nt], h2h[mt], h2l[mt], wv);
        }
    }
    // X4 as hi-only fp16 (final projection single-pass)
    u32 x4h[2][4];
#pragma unroll
    for (int mt = 0; mt < 2; mt++) d2a_hi(ca[mt][0], ca[mt][1], x4h[mt]);

    // ---- final: OUT = X4 @ fw + fb -> stage in smem, then dense copy-out ----
#pragma unroll
    for (int nt = 0; nt < 9; nt++) {
        int col = 8 * nt + col0;
        bool valid = (col < 66);
        float2 bv = valid ? *(const float2*)(fb + col) : make_float2(0.f, 0.f);
        u64 wv = g_frag[(T_FW + nt) * 32 + lane];
#pragma unroll
        for (int mt = 0; mt < 2; mt++) {
            float cf[4] = {bv.x, bv.y, bv.x, bv.y};
            mma_acc(cf, x4h[mt], wv);
            *(float2*)&sout[warp][16 * mt + r][col]     = make_float2(cf[0], cf[1]);
            *(float2*)&sout[warp][16 * mt + r + 8][col] = make_float2(cf[2], cf[3]);
        }
    }
    __syncwarp();
    // dense copy: 32 rows x 66 floats = 1056 float2, coalesced in gmem (33 full iters)
    {
        const float* src = &sout[warp][0][0];
        float* dst = out + ((size_t)(i << 10) + (size_t)jb) * 66ull;
#pragma unroll
        for (int it = 0; it < 33; it++) {
            int e = it * 32 + lane;
            int row = e / 33;
            int c2 = e - row * 33;
            float2 v = *(const float2*)(src + row * SOUT_STRIDE + 2 * c2);
            *(float2*)(dst + row * 66 + 2 * c2) = v;
        }
    }
}

extern "C" void kernel_launch(void* const* d_in, const int* in_sizes, int n_in,
                              void* d_out, int out_size) {
    const float* pc   = (const float*)d_in[0];
    const float* nrm  = (const float*)d_in[1];
    const float* dist = (const float*)d_in[2];
    const float* feat = (const float*)d_in[3];
    const float* w0   = (const float*)d_in[4];   const float* b0   = (const float*)d_in[5];
    const float* w1   = (const float*)d_in[6];   const float* b1   = (const float*)d_in[7];
    const float* l0w2 = (const float*)d_in[8];   const float* l0b2 = (const float*)d_in[9];
    const float* l1w1 = (const float*)d_in[10];  const float* l1b1 = (const float*)d_in[11];
    const float* l1w2 = (const float*)d_in[12];  const float* l1b2 = (const float*)d_in[13];
    const float* l2w0 = (const float*)d_in[14];  const float* l2b0 = (const float*)d_in[15];
    const float* l2w1 = (const float*)d_in[16];  const float* l2b1 = (const float*)d_in[17];
    const float* l2w2 = (const float*)d_in[18];  const float* l2b2 = (const float*)d_in[19];
    const float* fw   = (const float*)d_in[20];  const float* fb   = (const float*)d_in[21];
    float* out = (float*)d_out;

    prep<<<267, 256>>>(feat, w0, b0, w1, b1,
                       l0w2, l1w1, l1w2, l2w0, l2w1, l2w2, fw);
    ppf_main<<<8192, 128>>>(pc, nrm, dist, w0, w1,
                            l0b2, l1b1, l1b2, l2b0, l2b1, l2b2, fb, out);
}

// round 11
// speedup vs baseline: 1.5172x; 1.0921x over previous
#include <cuda_runtime.h>
#include <cuda_fp16.h>
#include <cstdint>

typedef unsigned long long u64;
typedef unsigned u32;

// ===== per-point separable layer0 tables, stored PERMUTED into fragment order =====
// index: point*32 + cc*8 + nt*2 + e   (original col c = 8*nt + 2*cc + e)
__device__ float g_A0[1024 * 32];
__device__ float g_B0[1024 * 32];
__device__ float g_A1[1024 * 32];
__device__ float g_B1[1024 * 32];

// ================= weight B-fragments (single fp16) =================
#define T_L0W2  0    // 2kt x 4nt
#define T_L1W1  8
#define T_L1W2  16
#define T_L2W0  24   // 2kt x 2nt
#define T_L2W1  28
#define T_L2W2  32   // 1kt x 2nt
#define T_FW    34   // 1kt x 9nt (N=66 pad 72)
#define N_TILES 43

__device__ u64 g_frag[N_TILES * 32];

__device__ __forceinline__ u32 h16b(float v) {
    return (u32)__half_as_ushort(__float2half_rn(v));
}

// ---- fused prep: blocks [0,256) = per-point tables; blocks [256,267) = frags ----
__global__ void prep(const float* __restrict__ feat,
                     const float* __restrict__ w0, const float* __restrict__ b0,
                     const float* __restrict__ w1, const float* __restrict__ b1,
                     const float* __restrict__ l0w2, const float* __restrict__ l1w1,
                     const float* __restrict__ l1w2, const float* __restrict__ l2w0,
                     const float* __restrict__ l2w1, const float* __restrict__ l2w2,
                     const float* __restrict__ fw) {
    int b = blockIdx.x;
    if (b < 256) {
        int t = b * 256 + threadIdx.x;          // 65536 threads
        int i = t >> 6, rem = t & 63, sel = rem >> 5, c = rem & 31;
        const float* f = feat + i * 40;
        const float* w = sel ? w1 : w0;
        float a = sel ? b1[c] : b0[c], bo = 0.f;
#pragma unroll
        for (int k = 0; k < 40; k++) {
            float fv = f[k];
            a  = fmaf(fv, w[k * 32 + c],        a);
            bo = fmaf(fv, w[(k + 40) * 32 + c], bo);
        }
        // permuted index: c = 8*nt + 2*cc + e  ->  cc*8 + nt*2 + e
        int p = ((c & 7) >> 1) * 8 + (c >> 3) * 2 + (c & 1);
        if (sel) { g_A1[i * 32 + p] = a; g_B1[i * 32 + p] = bo; }
        else     { g_A0[i * 32 + p] = a; g_B0[i * 32 + p] = bo; }
    } else {
        int e = (b - 256) * 256 + threadIdx.x;
        if (e >= N_TILES * 32) return;
        struct Spec { const float* w; int K, N, nnt, base, ntiles; };
        Spec sp[7] = {
            {l0w2, 32, 32, 4, T_L0W2, 8},
            {l1w1, 32, 32, 4, T_L1W1, 8},
            {l1w2, 32, 32, 4, T_L1W2, 8},
            {l2w0, 32, 16, 2, T_L2W0, 4},
            {l2w1, 32, 16, 2, T_L2W1, 4},
            {l2w2, 16, 16, 2, T_L2W2, 2},
            {fw,   16, 66, 9, T_FW,   9},
        };
        int tile = e >> 5, lane = e & 31;
        int si = 0;
        for (int q = 0; q < 7; q++)
            if (tile >= sp[q].base && tile < sp[q].base + sp[q].ntiles) si = q;
        const float* w = sp[si].w;
        int K = sp[si].K, N = sp[si].N, nnt = sp[si].nnt;
        int lt = tile - sp[si].base, kt = lt / nnt, nt = lt % nnt;
        int n = nt * 8 + (lane >> 2), cc = lane & 3;
        int ks[4] = {kt * 16 + 2 * cc, kt * 16 + 2 * cc + 1,
                     kt * 16 + 2 * cc + 8, kt * 16 + 2 * cc + 9};
        u32 bits[4];
#pragma unroll
        for (int q = 0; q < 4; q++) {
            int k = ks[q];
            float v = (k < K && n < N) ? w[k * N + n] : 0.f;
            bits[q] = h16b(v);
        }
        u32 lo = (bits[1] << 16) | bits[0];
        u32 hi = (bits[3] << 16) | bits[2];
        g_frag[e] = ((u64)hi << 32) | (u64)lo;
    }
}

// ================= MMA helpers (fp16 in, fp32 acc) =================
__device__ __forceinline__ void mma_acc(float c[4], const u32 a[4], u64 b) {
    u32 b0 = (u32)b, b1 = (u32)(b >> 32);
    asm volatile("mma.sync.aligned.m16n8k16.row.col.f32.f16.f16.f32 "
        "{%0,%1,%2,%3}, {%4,%5,%6,%7}, {%8,%9}, {%0,%1,%2,%3};"
        : "+f"(c[0]), "+f"(c[1]), "+f"(c[2]), "+f"(c[3])
        : "r"(a[0]), "r"(a[1]), "r"(a[2]), "r"(a[3]), "r"(b0), "r"(b1));
}
__device__ __forceinline__ void mma2(float c[4], const u32 ah[4], const u32 al[4], u64 w) {
    mma_acc(c, ah, w);
    mma_acc(c, al, w);
}

// pack (x0 low, x1 high) into fp16x2 hi, residue into lo
__device__ __forceinline__ void split2(float x0, float x1, u32& hi, u32& lo) {
    __half2 h = __floats2half2_rn(x0, x1);
    float2 f = __half22float2(h);
    __half2 l = __floats2half2_rn(x0 - f.x, x1 - f.y);
    hi = *reinterpret_cast<u32*>(&h);
    lo = *reinterpret_cast<u32*>(&l);
}
__device__ __forceinline__ u32 split2h(float x0, float x1) {
    __half2 h = __floats2half2_rn(x0, x1);
    return *reinterpret_cast<u32*>(&h);
}
__device__ __forceinline__ float2 h2f(u32 v) {
    __half2 h = *reinterpret_cast<__half2*>(&v);
    return __half22float2(h);
}

// D tiles (ntile 2kt, 2kt+1) -> A frag (ktile kt), hi+lo, optional relu
template<bool RELU>
__device__ __forceinline__ void d2a(const float* d0, const float* d1, u32* ah, u32* al) {
    float v0 = d0[0], v1 = d0[1], v2 = d0[2], v3 = d0[3];
    float w0 = d1[0], w1 = d1[1], w2 = d1[2], w3 = d1[3];
    if (RELU) {
        v0 = fmaxf(v0, 0.f); v1 = fmaxf(v1, 0.f); v2 = fmaxf(v2, 0.f); v3 = fmaxf(v3, 0.f);
        w0 = fmaxf(w0, 0.f); w1 = fmaxf(w1, 0.f); w2 = fmaxf(w2, 0.f); w3 = fmaxf(w3, 0.f);
    }
    split2(v0, v1, ah[0], al[0]);
    split2(v2, v3, ah[1], al[1]);
    split2(w0, w1, ah[2], al[2]);
    split2(w2, w3, ah[3], al[3]);
}
// hi-only A frag, optional relu
template<bool RELU>
__device__ __forceinline__ void d2a_h(const float* d0, const float* d1, u32* ah) {
    float v0 = d0[0], v1 = d0[1], v2 = d0[2], v3 = d0[3];
    float w0 = d1[0], w1 = d1[1], w2 = d1[2], w3 = d1[3];
    if (RELU) {
        v0 = fmaxf(v0, 0.f); v1 = fmaxf(v1, 0.f); v2 = fmaxf(v2, 0.f); v3 = fmaxf(v3, 0.f);
        w0 = fmaxf(w0, 0.f); w1 = fmaxf(w1, 0.f); w2 = fmaxf(w2, 0.f); w3 = fmaxf(w3, 0.f);
    }
    ah[0] = split2h(v0, v1);
    ah[1] = split2h(v2, v3);
    ah[2] = split2h(w0, w1);
    ah[3] = split2h(w2, w3);
}

#define SOUT_STRIDE 74   // 74 mod 32 = 10 -> conflict-free row stagger, float2-aligned

// ====== main kernel: warp = 32 pairs, tiled 4i x 8j (two m16 tiles of 2i x 8j) ======
// m-row mapping (tile mt): row r (<8) = pair (ib+2mt,   jb8+r)
//                          row r+8    = pair (ib+2mt+1, jb8+r)
__global__ void __launch_bounds__(128, 4) ppf_main(
    const float* __restrict__ pc, const float* __restrict__ nrm,
    const float* __restrict__ dist,
    const float* __restrict__ fc0w, const float* __restrict__ fc1w,
    const float* __restrict__ l0b2, const float* __restrict__ l1b1,
    const float* __restrict__ l1b2, const float* __restrict__ l2b0,
    const float* __restrict__ l2b1, const float* __restrict__ l2b2,
    const float* __restrict__ fb, float* __restrict__ out)
{
    __shared__ float sppf[4][32][4];
    __shared__ float sW1p[4][32];
    __shared__ float sW0p[4][32];
    __shared__ float sout[4][32][SOUT_STRIDE];
    const int tid = threadIdx.x;
    const int lane = tid & 31, warp = tid >> 5;
    const int bx = blockIdx.x;
    const int ib = (bx >> 5) << 2;                    // 4 i's per CTA
    const int jb8 = ((bx & 31) << 5) + (warp << 3);   // 8 j's per warp
    const int r = lane >> 2, cc = lane & 3;
    const int col0 = 2 * cc;

    // stage ppf-weight rows (80..83) of fc1/fc0
    if (tid < 128) {
        sW1p[tid >> 5][tid & 31] = fc1w[80 * 32 + tid];
        sW0p[tid >> 5][tid & 31] = fc0w[80 * 32 + tid];
    }

    // ---- PPF features: lane = i_loc*8 + j_loc ----
    {
        int i = ib + (lane >> 3);
        int j = jb8 + (lane & 7);
        float pcix = pc[3 * i], pciy = pc[3 * i + 1], pciz = pc[3 * i + 2];
        float nix = nrm[3 * i], niy = nrm[3 * i + 1], niz = nrm[3 * i + 2];
        float pcjx = pc[3 * j], pcjy = pc[3 * j + 1], pcjz = pc[3 * j + 2];
        float njx = nrm[3 * j], njy = nrm[3 * j + 1], njz = nrm[3 * j + 2];
        float dd = dist[(i << 10) + j];
        float inv = 1.0f / (dd + 1e-7f);
        float xx0 = pcix - pcjx, xx1 = pciy - pcjy, xx2 = pciz - pcjz;
        sppf[warp][lane][0] = (nix * xx0 + niy * xx1 + niz * xx2) * inv;
        sppf[warp][lane][1] = (njx * xx0 + njy * xx1 + njz * xx2) * inv;
        sppf[warp][lane][2] = nix * njx + niy * njy + niz * njz;
        sppf[warp][lane][3] = dd;
    }
    __syncthreads();

    // ppf rows this lane needs: pA -> row r (pair (ib+2mt, jb8+r)), pB -> row r+8
    float pA[2][4], pB[2][4];
#pragma unroll
    for (int mt = 0; mt < 2; mt++)
#pragma unroll
        for (int k = 0; k < 4; k++) {
            pA[mt][k] = sppf[warp][(2 * mt) * 8 + r][k];
            pB[mt][k] = sppf[warp][(2 * mt + 1) * 8 + r][k];
        }

    const int tb = (cc << 3);   // permuted table base offset for this cc

    // ---- layer0: X1 = relu(A1[i] + B1[j] + ppf@W1p)  (scalar fp32 ppf GEMM) ----
    float cx[2][4][4];
#pragma unroll
    for (int c4 = 0; c4 < 2; c4++) {
        // B row shared by both m-halves and both tiles
        float4 bv = ((const float4*)(g_B1 + ((jb8 + r) << 5) + tb))[c4];
#pragma unroll
        for (int mt = 0; mt < 2; mt++) {
            float4 ar = ((const float4*)(g_A1 + ((ib + 2 * mt) << 5) + tb))[c4];
            float4 as = ((const float4*)(g_A1 + ((ib + 2 * mt + 1) << 5) + tb))[c4];
#pragma unroll
            for (int h = 0; h < 2; h++) {
                int nt = 2 * c4 + h;
                int col = 8 * nt + col0;
                float bxv = h ? bv.z : bv.x, byv = h ? bv.w : bv.y;
                float arx = h ? ar.z : ar.x, ary = h ? ar.w : ar.y;
                float asx = h ? as.z : as.x, asy = h ? as.w : as.y;
                float c0 = arx + bxv, c1 = ary + byv;
                float c2 = asx + bxv, c3 = asy + byv;
#pragma unroll
                for (int k = 0; k < 4; k++) {
                    float2 wv = *(const float2*)&sW1p[k][col];
                    c0 = fmaf(pA[mt][k], wv.x, c0); c1 = fmaf(pA[mt][k], wv.y, c1);
                    c2 = fmaf(pB[mt][k], wv.x, c2); c3 = fmaf(pB[mt][k], wv.y, c3);
                }
                cx[mt][nt][0] = c0; cx[mt][nt][1] = c1;
                cx[mt][nt][2] = c2; cx[mt][nt][3] = c3;
            }
        }
    }
    u32 x1h[2][2][4], x1l[2][2][4];
#pragma unroll
    for (int mt = 0; mt < 2; mt++)
#pragma unroll
        for (int kt = 0; kt < 2; kt++)
            d2a<true>(cx[mt][2 * kt], cx[mt][2 * kt + 1], x1h[mt][kt], x1l[mt][kt]);

    // ---- residual R0 = A0[i] + B0[j] + ppf@W0p  (reuse cx) ----
#pragma unroll
    for (int c4 = 0; c4 < 2; c4++) {
        float4 bv = ((const float4*)(g_B0 + ((jb8 + r) << 5) + tb))[c4];
#pragma unroll
        for (int mt = 0; mt < 2; mt++) {
            float4 ar = ((const float4*)(g_A0 + ((ib + 2 * mt) << 5) + tb))[c4];
            float4 as = ((const float4*)(g_A0 + ((ib + 2 * mt + 1) << 5) + tb))[c4];
#pragma unroll
            for (int h = 0; h < 2; h++) {
                int nt = 2 * c4 + h;
                int col = 8 * nt + col0;
                float bxv = h ? bv.z : bv.x, byv = h ? bv.w : bv.y;
                float arx = h ? ar.z : ar.x, ary = h ? ar.w : ar.y;
                float asx = h ? as.z : as.x, asy = h ? as.w : as.y;
                float c0 = arx + bxv, c1 = ary + byv;
                float c2 = asx + bxv, c3 = asy + byv;
#pragma unroll
                for (int k = 0; k < 4; k++) {
                    float2 wv = *(const float2*)&sW0p[k][col];
                    c0 = fmaf(pA[mt][k], wv.x, c0); c1 = fmaf(pA[mt][k], wv.y, c1);
                    c2 = fmaf(pB[mt][k], wv.x, c2); c3 = fmaf(pB[mt][k], wv.y, c3);
                }
                cx[mt][nt][0] = c0; cx[mt][nt][1] = c1;
                cx[mt][nt][2] = c2; cx[mt][nt][3] = c3;
            }
        }
    }

    // ---- l0fc2: X2 = X1@W2 + b2 + R0 ----
#pragma unroll
    for (int nt = 0; nt < 4; nt++) {
        float2 bv = *(const float2*)(l0b2 + 8 * nt + col0);
#pragma unroll
        for (int mt = 0; mt < 2; mt++) {
            cx[mt][nt][0] += bv.x; cx[mt][nt][1] += bv.y;
            cx[mt][nt][2] += bv.x; cx[mt][nt][3] += bv.y;
        }
    }
#pragma unroll
    for (int kt = 0; kt < 2; kt++)
#pragma unroll
        for (int nt = 0; nt < 4; nt++) {
            u64 wv = g_frag[(T_L0W2 + kt * 4 + nt) * 32 + lane];
            mma2(cx[0][nt], x1h[0][kt], x1l[0][kt], wv);
            mma2(cx[1][nt], x1h[1][kt], x1l[1][kt], wv);
        }
    u32 x2h[2][2][4], x2l[2][2][4];
#pragma unroll
    for (int mt = 0; mt < 2; mt++)
#pragma unroll
        for (int kt = 0; kt < 2; kt++)
            d2a<false>(cx[mt][2 * kt], cx[mt][2 * kt + 1], x2h[mt][kt], x2l[mt][kt]);

    // ---- layer1 fc1: H = relu(X2@W1 + b1) -- accumulate in cx ----
#pragma unroll
    for (int nt = 0; nt < 4; nt++) {
        float2 bv = *(const float2*)(l1b1 + 8 * nt + col0);
#pragma unroll
        for (int mt = 0; mt < 2; mt++) {
            cx[mt][nt][0] = bv.x; cx[mt][nt][1] = bv.y;
            cx[mt][nt][2] = bv.x; cx[mt][nt][3] = bv.y;
        }
    }
#pragma unroll
    for (int kt = 0; kt < 2; kt++)
#pragma unroll
        for (int nt = 0; nt < 4; nt++) {
            u64 wv = g_frag[(T_L1W1 + kt * 4 + nt) * 32 + lane];
            mma2(cx[0][nt], x2h[0][kt], x2l[0][kt], wv);
            mma2(cx[1][nt], x2h[1][kt], x2l[1][kt], wv);
        }
    u32 hh[2][2][4];
#pragma unroll
    for (int mt = 0; mt < 2; mt++)
#pragma unroll
        for (int kt = 0; kt < 2; kt++)
            d2a_h<true>(cx[mt][2 * kt], cx[mt][2 * kt + 1], hh[mt][kt]);

    // ---- layer1 fc2: X3 = H@W2 + b2 + X2 (X2 reconstructed from x2h + x2l) ----
#pragma unroll
    for (int kt = 0; kt < 2; kt++)
#pragma unroll
        for (int h = 0; h < 2; h++) {
            int nt = 2 * kt + h;
            float2 bv = *(const float2*)(l1b2 + 8 * nt + col0);
#pragma unroll
            for (int mt = 0; mt < 2; mt++) {
                float2 hA = h2f(x2h[mt][kt][2 * h]),     lA = h2f(x2l[mt][kt][2 * h]);
                float2 hB = h2f(x2h[mt][kt][2 * h + 1]), lB = h2f(x2l[mt][kt][2 * h + 1]);
                cx[mt][nt][0] = bv.x + hA.x + lA.x;
                cx[mt][nt][1] = bv.y + hA.y + lA.y;
                cx[mt][nt][2] = bv.x + hB.x + lB.x;
                cx[mt][nt][3] = bv.y + hB.y + lB.y;
            }
        }
#pragma unroll
    for (int kt = 0; kt < 2; kt++)
#pragma unroll
        for (int nt = 0; nt < 4; nt++) {
            u64 wv = g_frag[(T_L1W2 + kt * 4 + nt) * 32 + lane];
            mma_acc(cx[0][nt], hh[0][kt], wv);
            mma_acc(cx[1][nt], hh[1][kt], wv);
        }
    u32 x3h[2][2][4], x3l[2][2][4];
#pragma unroll
    for (int mt = 0; mt < 2; mt++)
#pragma unroll
        for (int kt = 0; kt < 2; kt++)
            d2a<false>(cx[mt][2 * kt], cx[mt][2 * kt + 1], x3h[mt][kt], x3l[mt][kt]);

    // ---- layer2 ----
    float ca[2][2][4], cb[2][2][4];
#pragma unroll
    for (int nt = 0; nt < 2; nt++) {
        float2 b0v = *(const float2*)(l2b0 + 8 * nt + col0);
        float2 b1v = *(const float2*)(l2b1 + 8 * nt + col0);
#pragma unroll
        for (int mt = 0; mt < 2; mt++) {
            ca[mt][nt][0] = b0v.x; ca[mt][nt][1] = b0v.y;
            ca[mt][nt][2] = b0v.x; ca[mt][nt][3] = b0v.y;
            cb[mt][nt][0] = b1v.x; cb[mt][nt][1] = b1v.y;
            cb[mt][nt][2] = b1v.x; cb[mt][nt][3] = b1v.y;
        }
    }
#pragma unroll
    for (int kt = 0; kt < 2; kt++)
#pragma unroll
        for (int nt = 0; nt < 2; nt++) {
            u64 w0v = g_frag[(T_L2W0 + kt * 2 + nt) * 32 + lane];
            u64 w1v = g_frag[(T_L2W1 + kt * 2 + nt) * 32 + lane];
#pragma unroll
            for (int mt = 0; mt < 2; mt++) {
                mma2(ca[mt][nt], x3h[mt][kt], x3l[mt][kt], w0v);
                mma2(cb[mt][nt], x3h[mt][kt], x3l[mt][kt], w1v);
            }
        }
    u32 h2h[2][4];
#pragma unroll
    for (int mt = 0; mt < 2; mt++) d2a_h<true>(cb[mt][0], cb[mt][1], h2h[mt]);
#pragma unroll
    for (int nt = 0; nt < 2; nt++) {
        float2 bv = *(const float2*)(l2b2 + 8 * nt + col0);
        u64 wv = g_frag[(T_L2W2 + nt) * 32 + lane];
#pragma unroll
        for (int mt = 0; mt < 2; mt++) {
            ca[mt][nt][0] += bv.x; ca[mt][nt][1] += bv.y;
            ca[mt][nt][2] += bv.x; ca[mt][nt][3] += bv.y;
            mma_acc(ca[mt][nt], h2h[mt], wv);
        }
    }
    // X4 as hi-only fp16 (final projection single-pass)
    u32 x4h[2][4];
#pragma unroll
    for (int mt = 0; mt < 2; mt++) d2a_h<false>(ca[mt][0], ca[mt][1], x4h[mt]);

    // ---- final: OUT = X4 @ fw + fb -> stage in smem (row s = i_loc*8 + j_loc) ----
#pragma unroll
    for (int nt = 0; nt < 9; nt++) {
        int col = 8 * nt + col0;
        bool valid = (col < 66);
        float2 bv = valid ? *(const float2*)(fb + col) : make_float2(0.f, 0.f);
        u64 wv = g_frag[(T_FW + nt) * 32 + lane];
#pragma unroll
        for (int mt = 0; mt < 2; mt++) {
            float cf[4] = {bv.x, bv.y, bv.x, bv.y};
            mma_acc(cf, x4h[mt], wv);
            *(float2*)&sout[warp][(2 * mt) * 8 + r][col]     = make_float2(cf[0], cf[1]);
            *(float2*)&sout[warp][(2 * mt + 1) * 8 + r][col] = make_float2(cf[2], cf[3]);
        }
    }
    __syncwarp();
    // dense copy: 4 i-blocks, each 8 rows x 66 floats = 264 float2, coalesced
    {
        const float* src = &sout[warp][0][0];
#pragma unroll
        for (int blk = 0; blk < 4; blk++) {
            float* dst = out + (((size_t)(ib + blk) << 10) + (size_t)jb8) * 66ull;
#pragma unroll
            for (int it = 0; it < 9; it++) {
                int e = it * 32 + lane;
                if (e < 264) {
                    int row = e / 33;
                    int c2 = e - row * 33;
                    float2 v = *(const float2*)(src + (blk * 8 + row) * SOUT_STRIDE + 2 * c2);
                    *(float2*)(dst + row * 66 + 2 * c2) = v;
                }
            }
        }
    }
}

extern "C" void kernel_launch(void* const* d_in, const int* in_sizes, int n_in,
                              void* d_out, int out_size) {
    const float* pc   = (const float*)d_in[0];
    const float* nrm  = (const float*)d_in[1];
    const float* dist = (const float*)d_in[2];
    const float* feat = (const float*)d_in[3];
    const float* w0   = (const float*)d_in[4];   const float* b0   = (const float*)d_in[5];
    const float* w1   = (const float*)d_in[6];   const float* b1   = (const float*)d_in[7];
    const float* l0w2 = (const float*)d_in[8];   const float* l0b2 = (const float*)d_in[9];
    const float* l1w1 = (const float*)d_in[10];  const float* l1b1 = (const float*)d_in[11];
    const float* l1w2 = (const float*)d_in[12];  const float* l1b2 = (const float*)d_in[13];
    const float* l2w0 = (const float*)d_in[14];  const float* l2b0 = (const float*)d_in[15];
    const float* l2w1 = (const float*)d_in[16];  const float* l2b1 = (const float*)d_in[17];
    const float* l2w2 = (const float*)d_in[18];  const float* l2b2 = (const float*)d_in[19];
    const float* fw   = (const float*)d_in[20];  const float* fb   = (const float*)d_in[21];
    float* out = (float*)d_out;

    prep<<<267, 256>>>(feat, w0, b0, w1, b1,
                       l0w2, l1w1, l1w2, l2w0, l2w1, l2w2, fw);
    ppf_main<<<8192, 128>>>(pc, nrm, dist, w0, w1,
                            l0b2, l1b1, l1b2, l2b0, l2b1, l2b2, fb, out);
}

// round 12
// speedup vs baseline: 1.5840x; 1.0440x over previous
#include <cuda_runtime.h>
#include <cuda_fp16.h>
#include <cstdint>

typedef unsigned long long u64;
typedef unsigned u32;

// ===== per-point separable layer0 tables, stored PERMUTED into fragment order =====
// index: point*32 + cc*8 + nt*2 + e   (original col c = 8*nt + 2*cc + e)
__device__ float g_A0[1024 * 32];
__device__ float g_B0[1024 * 32];
__device__ float g_A1[1024 * 32];
__device__ float g_B1[1024 * 32];

// ================= weight B-fragments (single fp16) =================
#define T_L0W2  0    // 2kt x 4nt
#define T_L1W1  8
#define T_L1W2  16
#define T_L2W0  24   // 2kt x 2nt
#define T_L2W1  28
#define T_L2W2  32   // 1kt x 2nt
#define T_FW    34   // 1kt x 9nt (N=66 pad 72)
#define N_TILES 43

__device__ u64 g_frag[N_TILES * 32];

__device__ __forceinline__ u32 h16b(float v) {
    return (u32)__half_as_ushort(__float2half_rn(v));
}

// ---- fused prep: blocks [0,256) = per-point tables; blocks [256,267) = frags ----
__global__ void prep(const float* __restrict__ feat,
                     const float* __restrict__ w0, const float* __restrict__ b0,
                     const float* __restrict__ w1, const float* __restrict__ b1,
                     const float* __restrict__ l0w2, const float* __restrict__ l1w1,
                     const float* __restrict__ l1w2, const float* __restrict__ l2w0,
                     const float* __restrict__ l2w1, const float* __restrict__ l2w2,
                     const float* __restrict__ fw) {
    int b = blockIdx.x;
    if (b < 256) {
        int t = b * 256 + threadIdx.x;          // 65536 threads
        int i = t >> 6, rem = t & 63, sel = rem >> 5, c = rem & 31;
        const float* f = feat + i * 40;
        const float* w = sel ? w1 : w0;
        float a = sel ? b1[c] : b0[c], bo = 0.f;
#pragma unroll
        for (int k = 0; k < 40; k++) {
            float fv = f[k];
            a  = fmaf(fv, w[k * 32 + c],        a);
            bo = fmaf(fv, w[(k + 40) * 32 + c], bo);
        }
        // permuted index: c = 8*nt + 2*cc + e  ->  cc*8 + nt*2 + e
        int p = ((c & 7) >> 1) * 8 + (c >> 3) * 2 + (c & 1);
        if (sel) { g_A1[i * 32 + p] = a; g_B1[i * 32 + p] = bo; }
        else     { g_A0[i * 32 + p] = a; g_B0[i * 32 + p] = bo; }
    } else {
        int e = (b - 256) * 256 + threadIdx.x;
        if (e >= N_TILES * 32) return;
        struct Spec { const float* w; int K, N, nnt, base, ntiles; };
        Spec sp[7] = {
            {l0w2, 32, 32, 4, T_L0W2, 8},
            {l1w1, 32, 32, 4, T_L1W1, 8},
            {l1w2, 32, 32, 4, T_L1W2, 8},
            {l2w0, 32, 16, 2, T_L2W0, 4},
            {l2w1, 32, 16, 2, T_L2W1, 4},
            {l2w2, 16, 16, 2, T_L2W2, 2},
            {fw,   16, 66, 9, T_FW,   9},
        };
        int tile = e >> 5, lane = e & 31;
        int si = 0;
        for (int q = 0; q < 7; q++)
            if (tile >= sp[q].base && tile < sp[q].base + sp[q].ntiles) si = q;
        const float* w = sp[si].w;
        int K = sp[si].K, N = sp[si].N, nnt = sp[si].nnt;
        int lt = tile - sp[si].base, kt = lt / nnt, nt = lt % nnt;
        int n = nt * 8 + (lane >> 2), cc = lane & 3;
        int ks[4] = {kt * 16 + 2 * cc, kt * 16 + 2 * cc + 1,
                     kt * 16 + 2 * cc + 8, kt * 16 + 2 * cc + 9};
        u32 bits[4];
#pragma unroll
        for (int q = 0; q < 4; q++) {
            int k = ks[q];
            float v = (k < K && n < N) ? w[k * N + n] : 0.f;
            bits[q] = h16b(v);
        }
        u32 lo = (bits[1] << 16) | bits[0];
        u32 hi = (bits[3] << 16) | bits[2];
        g_frag[e] = ((u64)hi << 32) | (u64)lo;
    }
}

// ================= MMA helpers (fp16 in, fp32 acc) =================
__device__ __forceinline__ void mma_acc(float c[4], const u32 a[4], u64 b) {
    u32 b0 = (u32)b, b1 = (u32)(b >> 32);
    asm volatile("mma.sync.aligned.m16n8k16.row.col.f32.f16.f16.f32 "
        "{%0,%1,%2,%3}, {%4,%5,%6,%7}, {%8,%9}, {%0,%1,%2,%3};"
        : "+f"(c[0]), "+f"(c[1]), "+f"(c[2]), "+f"(c[3])
        : "r"(a[0]), "r"(a[1]), "r"(a[2]), "r"(a[3]), "r"(b0), "r"(b1));
}
__device__ __forceinline__ void mma2(float c[4], const u32 ah[4], const u32 al[4], u64 w) {
    mma_acc(c, ah, w);
    mma_acc(c, al, w);
}

// pack (x0 low, x1 high) into fp16x2 hi, residue into lo
__device__ __forceinline__ void split2(float x0, float x1, u32& hi, u32& lo) {
    __half2 h = __floats2half2_rn(x0, x1);
    float2 f = __half22float2(h);
    __half2 l = __floats2half2_rn(x0 - f.x, x1 - f.y);
    hi = *reinterpret_cast<u32*>(&h);
    lo = *reinterpret_cast<u32*>(&l);
}
__device__ __forceinline__ u32 split2h(float x0, float x1) {
    __half2 h = __floats2half2_rn(x0, x1);
    return *reinterpret_cast<u32*>(&h);
}
__device__ __forceinline__ float2 h2f(u32 v) {
    __half2 h = *reinterpret_cast<__half2*>(&v);
    return __half22float2(h);
}

// D tiles (ntile 2kt, 2kt+1) -> A frag (ktile kt), hi+lo, optional relu
template<bool RELU>
__device__ __forceinline__ void d2a(const float* d0, const float* d1, u32* ah, u32* al) {
    float v0 = d0[0], v1 = d0[1], v2 = d0[2], v3 = d0[3];
    float w0 = d1[0], w1 = d1[1], w2 = d1[2], w3 = d1[3];
    if (RELU) {
        v0 = fmaxf(v0, 0.f); v1 = fmaxf(v1, 0.f); v2 = fmaxf(v2, 0.f); v3 = fmaxf(v3, 0.f);
        w0 = fmaxf(w0, 0.f); w1 = fmaxf(w1, 0.f); w2 = fmaxf(w2, 0.f); w3 = fmaxf(w3, 0.f);
    }
    split2(v0, v1, ah[0], al[0]);
    split2(v2, v3, ah[1], al[1]);
    split2(w0, w1, ah[2], al[2]);
    split2(w2, w3, ah[3], al[3]);
}
// hi-only A frag, optional relu
template<bool RELU>
__device__ __forceinline__ void d2a_h(const float* d0, const float* d1, u32* ah) {
    float v0 = d0[0], v1 = d0[1], v2 = d0[2], v3 = d0[3];
    float w0 = d1[0], w1 = d1[1], w2 = d1[2], w3 = d1[3];
    if (RELU) {
        v0 = fmaxf(v0, 0.f); v1 = fmaxf(v1, 0.f); v2 = fmaxf(v2, 0.f); v3 = fmaxf(v3, 0.f);
        w0 = fmaxf(w0, 0.f); w1 = fmaxf(w1, 0.f); w2 = fmaxf(w2, 0.f); w3 = fmaxf(w3, 0.f);
    }
    ah[0] = split2h(v0, v1);
    ah[1] = split2h(v2, v3);
    ah[2] = split2h(w0, w1);
    ah[3] = split2h(w2, w3);
}

#define SOUT_STRIDE 74   // 74 mod 32 = 10 -> conflict-free row stagger, float2-aligned

// ====== main kernel: warp = 32 pairs, tiled 4i x 8j (two m16 tiles of 2i x 8j) ======
__global__ void __launch_bounds__(128, 4) ppf_main(
    const float* __restrict__ pc, const float* __restrict__ nrm,
    const float* __restrict__ dist,
    const float* __restrict__ fc0w, const float* __restrict__ fc1w,
    const float* __restrict__ l0b2, const float* __restrict__ l1b1,
    const float* __restrict__ l1b2, const float* __restrict__ l2b0,
    const float* __restrict__ l2b1, const float* __restrict__ l2b2,
    const float* __restrict__ fb, float* __restrict__ out)
{
    __shared__ float sppf[4][32][4];
    __shared__ float sW1p[4][32];
    __shared__ float sW0p[4][32];
    __shared__ float sout[4][32][SOUT_STRIDE];
    const int tid = threadIdx.x;
    const int lane = tid & 31, warp = tid >> 5;
    const int bx = blockIdx.x;
    const int ib = (bx >> 5) << 2;                    // 4 i's per CTA
    const int jb8 = ((bx & 31) << 5) + (warp << 3);   // 8 j's per warp
    const int r = lane >> 2, cc = lane & 3;
    const int col0 = 2 * cc;

    // stage ppf-weight rows (80..83) of fc1/fc0
    if (tid < 128) {
        sW1p[tid >> 5][tid & 31] = fc1w[80 * 32 + tid];
        sW0p[tid >> 5][tid & 31] = fc0w[80 * 32 + tid];
    }

    // ---- PPF features: lane = i_loc*8 + j_loc ----
    {
        int i = ib + (lane >> 3);
        int j = jb8 + (lane & 7);
        float pcix = pc[3 * i], pciy = pc[3 * i + 1], pciz = pc[3 * i + 2];
        float nix = nrm[3 * i], niy = nrm[3 * i + 1], niz = nrm[3 * i + 2];
        float pcjx = pc[3 * j], pcjy = pc[3 * j + 1], pcjz = pc[3 * j + 2];
        float njx = nrm[3 * j], njy = nrm[3 * j + 1], njz = nrm[3 * j + 2];
        float dd = dist[(i << 10) + j];
        float inv = 1.0f / (dd + 1e-7f);
        float xx0 = pcix - pcjx, xx1 = pciy - pcjy, xx2 = pciz - pcjz;
        sppf[warp][lane][0] = (nix * xx0 + niy * xx1 + niz * xx2) * inv;
        sppf[warp][lane][1] = (njx * xx0 + njy * xx1 + njz * xx2) * inv;
        sppf[warp][lane][2] = nix * njx + niy * njy + niz * njz;
        sppf[warp][lane][3] = dd;
    }
    __syncthreads();

    // ppf rows this lane needs: pA -> row r (pair (ib+2mt, jb8+r)), pB -> row r+8
    float pA[2][4], pB[2][4];
#pragma unroll
    for (int mt = 0; mt < 2; mt++)
#pragma unroll
        for (int k = 0; k < 4; k++) {
            pA[mt][k] = sppf[warp][(2 * mt) * 8 + r][k];
            pB[mt][k] = sppf[warp][(2 * mt + 1) * 8 + r][k];
        }

    const int tb = (cc << 3);   // permuted table base offset for this cc

    // ---- layer0: X1 = relu(A1[i] + B1[j] + ppf@W1p)  (scalar fp32 ppf GEMM) ----
    float cx[2][4][4];
#pragma unroll
    for (int c4 = 0; c4 < 2; c4++) {
        float4 bv = ((const float4*)(g_B1 + ((jb8 + r) << 5) + tb))[c4];
#pragma unroll
        for (int mt = 0; mt < 2; mt++) {
            float4 ar = ((const float4*)(g_A1 + ((ib + 2 * mt) << 5) + tb))[c4];
            float4 as = ((const float4*)(g_A1 + ((ib + 2 * mt + 1) << 5) + tb))[c4];
#pragma unroll
            for (int h = 0; h < 2; h++) {
                int nt = 2 * c4 + h;
                int col = 8 * nt + col0;
                float bxv = h ? bv.z : bv.x, byv = h ? bv.w : bv.y;
                float arx = h ? ar.z : ar.x, ary = h ? ar.w : ar.y;
                float asx = h ? as.z : as.x, asy = h ? as.w : as.y;
                float c0 = arx + bxv, c1 = ary + byv;
                float c2 = asx + bxv, c3 = asy + byv;
#pragma unroll
                for (int k = 0; k < 4; k++) {
                    float2 wv = *(const float2*)&sW1p[k][col];
                    c0 = fmaf(pA[mt][k], wv.x, c0); c1 = fmaf(pA[mt][k], wv.y, c1);
                    c2 = fmaf(pB[mt][k], wv.x, c2); c3 = fmaf(pB[mt][k], wv.y, c3);
                }
                cx[mt][nt][0] = c0; cx[mt][nt][1] = c1;
                cx[mt][nt][2] = c2; cx[mt][nt][3] = c3;
            }
        }
    }
    // X1 hi-only (post-relu hidden, single consumer)
    u32 x1h[2][2][4];
#pragma unroll
    for (int mt = 0; mt < 2; mt++)
#pragma unroll
        for (int kt = 0; kt < 2; kt++)
            d2a_h<true>(cx[mt][2 * kt], cx[mt][2 * kt + 1], x1h[mt][kt]);

    // ---- residual R0 = A0[i] + B0[j] + ppf@W0p  (reuse cx) ----
#pragma unroll
    for (int c4 = 0; c4 < 2; c4++) {
        float4 bv = ((const float4*)(g_B0 + ((jb8 + r) << 5) + tb))[c4];
#pragma unroll
        for (int mt = 0; mt < 2; mt++) {
            float4 ar = ((const float4*)(g_A0 + ((ib + 2 * mt) << 5) + tb))[c4];
            float4 as = ((const float4*)(g_A0 + ((ib + 2 * mt + 1) << 5) + tb))[c4];
#pragma unroll
            for (int h = 0; h < 2; h++) {
                int nt = 2 * c4 + h;
                int col = 8 * nt + col0;
                float bxv = h ? bv.z : bv.x, byv = h ? bv.w : bv.y;
                float arx = h ? ar.z : ar.x, ary = h ? ar.w : ar.y;
                float asx = h ? as.z : as.x, asy = h ? as.w : as.y;
                float c0 = arx + bxv, c1 = ary + byv;
                float c2 = asx + bxv, c3 = asy + byv;
#pragma unroll
                for (int k = 0; k < 4; k++) {
                    float2 wv = *(const float2*)&sW0p[k][col];
                    c0 = fmaf(pA[mt][k], wv.x, c0); c1 = fmaf(pA[mt][k], wv.y, c1);
                    c2 = fmaf(pB[mt][k], wv.x, c2); c3 = fmaf(pB[mt][k], wv.y, c3);
                }
                cx[mt][nt][0] = c0; cx[mt][nt][1] = c1;
                cx[mt][nt][2] = c2; cx[mt][nt][3] = c3;
            }
        }
    }

    // ---- l0fc2: X2 = X1@W2 + b2 + R0  (hi-only A) ----
#pragma unroll
    for (int nt = 0; nt < 4; nt++) {
        float2 bv = *(const float2*)(l0b2 + 8 * nt + col0);
#pragma unroll
        for (int mt = 0; mt < 2; mt++) {
            cx[mt][nt][0] += bv.x; cx[mt][nt][1] += bv.y;
            cx[mt][nt][2] += bv.x; cx[mt][nt][3] += bv.y;
        }
    }
#pragma unroll
    for (int kt = 0; kt < 2; kt++)
#pragma unroll
        for (int nt = 0; nt < 4; nt++) {
            u64 wv = g_frag[(T_L0W2 + kt * 4 + nt) * 32 + lane];
            mma_acc(cx[0][nt], x1h[0][kt], wv);
            mma_acc(cx[1][nt], x1h[1][kt], wv);
        }
    u32 x2h[2][2][4], x2l[2][2][4];
#pragma unroll
    for (int mt = 0; mt < 2; mt++)
#pragma unroll
        for (int kt = 0; kt < 2; kt++)
            d2a<false>(cx[mt][2 * kt], cx[mt][2 * kt + 1], x2h[mt][kt], x2l[mt][kt]);

    // ---- layer1 fc1: H = relu(X2@W1 + b1) -- accumulate in cx ----
#pragma unroll
    for (int nt = 0; nt < 4; nt++) {
        float2 bv = *(const float2*)(l1b1 + 8 * nt + col0);
#pragma unroll
        for (int mt = 0; mt < 2; mt++) {
            cx[mt][nt][0] = bv.x; cx[mt][nt][1] = bv.y;
            cx[mt][nt][2] = bv.x; cx[mt][nt][3] = bv.y;
        }
    }
#pragma unroll
    for (int kt = 0; kt < 2; kt++)
#pragma unroll
        for (int nt = 0; nt < 4; nt++) {
            u64 wv = g_frag[(T_L1W1 + kt * 4 + nt) * 32 + lane];
            mma2(cx[0][nt], x2h[0][kt], x2l[0][kt], wv);
            mma2(cx[1][nt], x2h[1][kt], x2l[1][kt], wv);
        }
    u32 hh[2][2][4];
#pragma unroll
    for (int mt = 0; mt < 2; mt++)
#pragma unroll
        for (int kt = 0; kt < 2; kt++)
            d2a_h<true>(cx[mt][2 * kt], cx[mt][2 * kt + 1], hh[mt][kt]);

    // ---- layer1 fc2: X3 = H@W2 + b2 + X2 (X2 reconstructed from x2h + x2l) ----
#pragma unroll
    for (int kt = 0; kt < 2; kt++)
#pragma unroll
        for (int h = 0; h < 2; h++) {
            int nt = 2 * kt + h;
            float2 bv = *(const float2*)(l1b2 + 8 * nt + col0);
#pragma unroll
            for (int mt = 0; mt < 2; mt++) {
                float2 hA = h2f(x2h[mt][kt][2 * h]),     lA = h2f(x2l[mt][kt][2 * h]);
                float2 hB = h2f(x2h[mt][kt][2 * h + 1]), lB = h2f(x2l[mt][kt][2 * h + 1]);
                cx[mt][nt][0] = bv.x + hA.x + lA.x;
                cx[mt][nt][1] = bv.y + hA.y + lA.y;
                cx[mt][nt][2] = bv.x + hB.x + lB.x;
                cx[mt][nt][3] = bv.y + hB.y + lB.y;
            }
        }
#pragma unroll
    for (int kt = 0; kt < 2; kt++)
#pragma unroll
        for (int nt = 0; nt < 4; nt++) {
            u64 wv = g_frag[(T_L1W2 + kt * 4 + nt) * 32 + lane];
            mma_acc(cx[0][nt], hh[0][kt], wv);
            mma_acc(cx[1][nt], hh[1][kt], wv);
        }
    // X3 hi-only (consumed only as A operand of l2fc0/l2fc1)
    u32 x3h[2][2][4];
#pragma unroll
    for (int mt = 0; mt < 2; mt++)
#pragma unroll
        for (int kt = 0; kt < 2; kt++)
            d2a_h<false>(cx[mt][2 * kt], cx[mt][2 * kt + 1], x3h[mt][kt]);

    // ---- layer2 ----
    float ca[2][2][4], cb[2][2][4];
#pragma unroll
    for (int nt = 0; nt < 2; nt++) {
        float2 b0v = *(const float2*)(l2b0 + 8 * nt + col0);
        float2 b1v = *(const float2*)(l2b1 + 8 * nt + col0);
#pragma unroll
        for (int mt = 0; mt < 2; mt++) {
            ca[mt][nt][0] = b0v.x; ca[mt][nt][1] = b0v.y;
            ca[mt][nt][2] = b0v.x; ca[mt][nt][3] = b0v.y;
            cb[mt][nt][0] = b1v.x; cb[mt][nt][1] = b1v.y;
            cb[mt][nt][2] = b1v.x; cb[mt][nt][3] = b1v.y;
        }
    }
#pragma unroll
    for (int kt = 0; kt < 2; kt++)
#pragma unroll
        for (int nt = 0; nt < 2; nt++) {
            u64 w0v = g_frag[(T_L2W0 + kt * 2 + nt) * 32 + lane];
            u64 w1v = g_frag[(T_L2W1 + kt * 2 + nt) * 32 + lane];
#pragma unroll
            for (int mt = 0; mt < 2; mt++) {
                mma_acc(ca[mt][nt], x3h[mt][kt], w0v);
                mma_acc(cb[mt][nt], x3h[mt][kt], w1v);
            }
        }
    u32 h2h[2][4];
#pragma unroll
    for (int mt = 0; mt < 2; mt++) d2a_h<true>(cb[mt][0], cb[mt][1], h2h[mt]);
#pragma unroll
    for (int nt = 0; nt < 2; nt++) {
        float2 bv = *(const float2*)(l2b2 + 8 * nt + col0);
        u64 wv = g_frag[(T_L2W2 + nt) * 32 + lane];
#pragma unroll
        for (int mt = 0; mt < 2; mt++) {
            ca[mt][nt][0] += bv.x; ca[mt][nt][1] += bv.y;
            ca[mt][nt][2] += bv.x; ca[mt][nt][3] += bv.y;
            mma_acc(ca[mt][nt], h2h[mt], wv);
        }
    }
    // X4 hi-only
    u32 x4h[2][4];
#pragma unroll
    for (int mt = 0; mt < 2; mt++) d2a_h<false>(ca[mt][0], ca[mt][1], x4h[mt]);

    // ---- final: OUT = X4 @ fw + fb -> stage in smem (row s = i_loc*8 + j_loc) ----
#pragma unroll
    for (int nt = 0; nt < 9; nt++) {
        int col = 8 * nt + col0;
        bool valid = (col < 66);
        float2 bv = valid ? *(const float2*)(fb + col) : make_float2(0.f, 0.f);
        u64 wv = g_frag[(T_FW + nt) * 32 + lane];
#pragma unroll
        for (int mt = 0; mt < 2; mt++) {
            float cf[4] = {bv.x, bv.y, bv.x, bv.y};
            mma_acc(cf, x4h[mt], wv);
            *(float2*)&sout[warp][(2 * mt) * 8 + r][col]     = make_float2(cf[0], cf[1]);
            *(float2*)&sout[warp][(2 * mt + 1) * 8 + r][col] = make_float2(cf[2], cf[3]);
        }
    }
    __syncwarp();
    // dense copy, division-free: per i-block, 8 full-width float2 rows + 8-lane tail
    {
        const float* src = &sout[warp][0][0];
#pragma unroll
        for (int blk = 0; blk < 4; blk++) {
            float* dst = out + (((size_t)(ib + blk) << 10) + (size_t)jb8) * 66ull;
#pragma unroll
            for (int row = 0; row < 8; row++) {
                float2 v = *(const float2*)(src + (blk * 8 + row) * SOUT_STRIDE + 2 * lane);
                *(float2*)(dst + row * 66 + 2 * lane) = v;
            }
            if (lane < 8) {
                float2 v = *(const float2*)(src + (blk * 8 + lane) * SOUT_STRIDE + 64);
                *(float2*)(dst + lane * 66 + 64) = v;
            }
        }
    }
}

extern "C" void kernel_launch(void* const* d_in, const int* in_sizes, int n_in,
                              void* d_out, int out_size) {
    const float* pc   = (const float*)d_in[0];
    const float* nrm  = (const float*)d_in[1];
    const float* dist = (const float*)d_in[2];
    const float* feat = (const float*)d_in[3];
    const float* w0   = (const float*)d_in[4];   const float* b0   = (const float*)d_in[5];
    const float* w1   = (const float*)d_in[6];   const float* b1   = (const float*)d_in[7];
    const float* l0w2 = (const float*)d_in[8];   const float* l0b2 = (const float*)d_in[9];
    const float* l1w1 = (const float*)d_in[10];  const float* l1b1 = (const float*)d_in[11];
    const float* l1w2 = (const float*)d_in[12];  const float* l1b2 = (const float*)d_in[13];
    const float* l2w0 = (const float*)d_in[14];  const float* l2b0 = (const float*)d_in[15];
    const float* l2w1 = (const float*)d_in[16];  const float* l2b1 = (const float*)d_in[17];
    const float* l2w2 = (const float*)d_in[18];  const float* l2b2 = (const float*)d_in[19];
    const float* fw   = (const float*)d_in[20];  const float* fb   = (const float*)d_in[21];
    float* out = (float*)d_out;

    prep<<<267, 256>>>(feat, w0, b0, w1, b1,
                       l0w2, l1w1, l1w2, l2w0, l2w1, l2w2, fw);
    ppf_main<<<8192, 128>>>(pc, nrm, dist, w0, w1,
                            l0b2, l1b1, l1b2, l2b0, l2b1, l2b2, fb, out);
}